// round 1
// baseline (speedup 1.0000x reference)
#include <cuda_runtime.h>
#include <cstdint>
#include <cstddef>

// ---------------- problem constants ----------------
#define NODE_NUM 232965
#define INPUT_DIM 602
#define HIDDEN_DIM 256
#define OUTPUT_DIM 41
#define BATCH 256
#define SCOPE 128
#define KSAMP 10
#define N1 2560      /* BATCH*KSAMP */
#define N2 25600     /* N1*KSAMP */

// ---------------- device scratch (static; no allocations) ----------------
__device__ float    d_M[INPUT_DIM * INPUT_DIM];       // a0*W W^T + a1*W2 W2^T
__device__ float    d_u[N1 * INPUT_DIM];              // projected src features
__device__ float    d_logatt[N1 * SCOPE];
__device__ int      d_front1[N1];
__device__ int      d_front2[N2];
__device__ float    d_adjL1[BATCH * KSAMP];           // adj_list[1]
__device__ float    d_adjL0[N1 * KSAMP];              // adj_list[0]
__device__ float    d_Xa[N1 * INPUT_DIM];
__device__ float    d_X1[N1 * HIDDEN_DIM];
__device__ float    d_Xb[BATCH * HIDDEN_DIM];
__device__ float    d_a[3];
__device__ unsigned d_keys[4];                        // sk1.{hi,lo}, sk2.{hi,lo}

// ---------------- threefry2x32 (JAX-exact) ----------------
__device__ __forceinline__ uint2 threefry(unsigned k0, unsigned k1,
                                          unsigned c0, unsigned c1) {
    unsigned ks2 = k0 ^ k1 ^ 0x1BD11BDAu;
    unsigned x0 = c0 + k0, x1 = c1 + k1;
#define TF_R(r) { x0 += x1; x1 = (x1 << (r)) | (x1 >> (32 - (r))); x1 ^= x0; }
    TF_R(13) TF_R(15) TF_R(26) TF_R(6)
    x0 += k1;  x1 += ks2 + 1u;
    TF_R(17) TF_R(29) TF_R(16) TF_R(24)
    x0 += ks2; x1 += k0 + 2u;
    TF_R(13) TF_R(15) TF_R(26) TF_R(6)
    x0 += k0;  x1 += k1 + 3u;
    TF_R(17) TF_R(29) TF_R(16) TF_R(24)
    x0 += k1;  x1 += ks2 + 4u;
    TF_R(13) TF_R(15) TF_R(26) TF_R(6)
    x0 += ks2; x1 += k0 + 5u;
#undef TF_R
    return make_uint2(x0, x1);
}

// ---------------- setup: softmax(a), key chain ----------------
__global__ void setup_kernel(const float* __restrict__ sa) {
    float v0 = sa[0], v1 = sa[1], v2 = sa[2];
    float m = fmaxf(v0, fmaxf(v1, v2));
    float e0 = expf(v0 - m), e1 = expf(v1 - m), e2 = expf(v2 - m);
    float s = e0 + e1 + e2;
    d_a[0] = e0 / s; d_a[1] = e1 / s; d_a[2] = e2 / s;
    // key(42) -> (0,42). partitionable split: child i = TF(key, 0, i)
    uint2 key1 = threefry(0u, 42u, 0u, 0u);
    uint2 sk1  = threefry(0u, 42u, 0u, 1u);
    uint2 sk2  = threefry(key1.x, key1.y, 0u, 1u);
    d_keys[0] = sk1.x; d_keys[1] = sk1.y;
    d_keys[2] = sk2.x; d_keys[3] = sk2.y;
}

// ---------------- M = a0 * Wa Wa^T + a1 * Wb Wb^T  (602x602, K=256) ----------------
__global__ void build_M_kernel(const float* __restrict__ Wa,
                               const float* __restrict__ Wb) {
    __shared__ float Fs[32][17];
    __shared__ float Gs[32][17];
    int f0 = blockIdx.y * 32, g0 = blockIdx.x * 32;
    int tid = threadIdx.x;
    int tx = tid & 15, ty = tid >> 4;
    float acc[2][2][2] = {};
    for (int p = 0; p < 2; p++) {
        const float* W = p ? Wb : Wa;
        for (int k0 = 0; k0 < HIDDEN_DIM; k0 += 16) {
#pragma unroll
            for (int e = 0; e < 2; e++) {
                int idx = tid + e * 256;      // 0..511
                int r = idx >> 4, c = idx & 15;
                Fs[r][c] = (f0 + r < INPUT_DIM) ? W[(size_t)(f0 + r) * HIDDEN_DIM + k0 + c] : 0.f;
                Gs[r][c] = (g0 + r < INPUT_DIM) ? W[(size_t)(g0 + r) * HIDDEN_DIM + k0 + c] : 0.f;
            }
            __syncthreads();
#pragma unroll
            for (int c = 0; c < 16; c++)
#pragma unroll
                for (int i = 0; i < 2; i++)
#pragma unroll
                    for (int j = 0; j < 2; j++)
                        acc[p][i][j] += Fs[ty * 2 + i][c] * Gs[tx * 2 + j][c];
            __syncthreads();
        }
    }
    float a0 = d_a[0], a1 = d_a[1];
#pragma unroll
    for (int i = 0; i < 2; i++)
#pragma unroll
        for (int j = 0; j < 2; j++) {
            int f = f0 + ty * 2 + i, g = g0 + tx * 2 + j;
            if (f < INPUT_DIM && g < INPUT_DIM)
                d_M[(size_t)f * INPUT_DIM + g] = a0 * acc[0][i][j] + a1 * acc[1][i][j];
        }
}

// ---------------- generic tiled SGEMM with optional row-gather + relu ----------------
// C[M,N] = gatherA(A)[M,K] @ B[K,N]
__global__ void sgemm_kernel(const float* __restrict__ A, const int* __restrict__ rowidx,
                             const float* __restrict__ B, float* __restrict__ C,
                             int M, int N, int K, int lda, int ldb, int ldc, int relu) {
    __shared__ float As[16][64];
    __shared__ float Bs[16][64];
    int tid = threadIdx.x;
    int row0 = blockIdx.y * 64, col0 = blockIdx.x * 64;
    int tx = tid & 15, ty = tid >> 4;
    int ar = tid >> 2;             // 0..63
    int ac = (tid & 3) * 4;        // 0,4,8,12
    int bk = tid >> 4;             // 0..15
    int bc = (tid & 15) * 4;
    int grow = row0 + ar;
    const float* Arow = nullptr;
    if (grow < M) {
        int r = rowidx ? rowidx[grow] : grow;
        Arow = A + (size_t)r * lda;
    }
    float acc[4][4] = {};
    for (int k0 = 0; k0 < K; k0 += 16) {
#pragma unroll
        for (int i = 0; i < 4; i++) {
            int k = k0 + ac + i;
            As[ac + i][ar] = (Arow != nullptr && k < K) ? Arow[k] : 0.f;
        }
        int kb = k0 + bk;
#pragma unroll
        for (int i = 0; i < 4; i++) {
            int c = col0 + bc + i;
            Bs[bk][bc + i] = (kb < K && c < N) ? B[(size_t)kb * ldb + c] : 0.f;
        }
        __syncthreads();
#pragma unroll
        for (int kk = 0; kk < 16; kk++) {
            float4 av = *reinterpret_cast<const float4*>(&As[kk][ty * 4]);
            float4 bv = *reinterpret_cast<const float4*>(&Bs[kk][tx * 4]);
            float a[4] = {av.x, av.y, av.z, av.w};
            float b[4] = {bv.x, bv.y, bv.z, bv.w};
#pragma unroll
            for (int i = 0; i < 4; i++)
#pragma unroll
                for (int j = 0; j < 4; j++)
                    acc[i][j] = fmaf(a[i], b[j], acc[i][j]);
        }
        __syncthreads();
    }
#pragma unroll
    for (int i = 0; i < 4; i++) {
        int r = row0 + ty * 4 + i;
        if (r >= M) continue;
#pragma unroll
        for (int j = 0; j < 4; j++) {
            int c = col0 + tx * 4 + j;
            if (c < N) {
                float v = acc[i][j];
                if (relu) v = fmaxf(v, 0.f);
                C[(size_t)r * ldc + c] = v;
            }
        }
    }
}

// ---------------- attention: logatt[n,s] = log(relu(u[n].t[n,s] + a2*w) + 1e-9) --------
__global__ void att_kernel(const float* __restrict__ feature,
                           const int* __restrict__ edge,
                           const float* __restrict__ weight,
                           const int* __restrict__ nodes,
                           const float* __restrict__ u,
                           float* __restrict__ logatt) {
    int b = blockIdx.x;
    __shared__ float us[INPUT_DIM];
    int row = nodes[b];
    const float* urow = u + (size_t)b * INPUT_DIM;
    for (int i = threadIdx.x; i < INPUT_DIM; i += blockDim.x) us[i] = urow[i];
    __syncthreads();
    float a2 = d_a[2];
    int warp = threadIdx.x >> 5, lane = threadIdx.x & 31;
    for (int s = warp; s < SCOPE; s += 8) {
        int nb = edge[(size_t)row * SCOPE + s];
        const float2* t2 = reinterpret_cast<const float2*>(feature + (size_t)nb * INPUT_DIM);
        float sum = 0.f;
        for (int j = lane; j < INPUT_DIM / 2; j += 32) {
            float2 v = t2[j];
            sum = fmaf(us[2 * j], v.x, sum);
            sum = fmaf(us[2 * j + 1], v.y, sum);
        }
#pragma unroll
        for (int o = 16; o; o >>= 1) sum += __shfl_down_sync(0xffffffffu, sum, o);
        if (lane == 0) {
            float att = sum + a2 * weight[(size_t)row * SCOPE + s];
            att = fmaxf(att, 0.f) + 1e-9f;
            logatt[(size_t)b * SCOPE + s] = logf(att);
        }
    }
}

// ---------------- gumbel-max sampling (JAX categorical, partitionable threefry) --------
__global__ void sample_kernel(const float* __restrict__ logatt,
                              const int* __restrict__ nodes,
                              const int* __restrict__ edge,
                              const float* __restrict__ weight,
                              int n, int key_off,
                              int* __restrict__ frontier_next,
                              float* __restrict__ adj) {
    int b = blockIdx.x;
    int j = threadIdx.x;               // 128 threads = SCOPE
    __shared__ float sval[SCOPE];
    __shared__ int   sidx[SCOPE];
    __shared__ int   cols[KSAMP];
    unsigned k0 = d_keys[key_off], k1 = d_keys[key_off + 1];
    float la = logatt[(size_t)b * SCOPE + j];
    const float TINY = 1.1754943508222875e-38f;
    for (int k = 0; k < KSAMP; k++) {
        // counter = linear index into gumbel tensor of shape (KSAMP, n, SCOPE)
        unsigned p = (unsigned)(((unsigned)(k * n + b)) * SCOPE + (unsigned)j);
        uint2 o = threefry(k0, k1, 0u, p);
        unsigned bits = o.x ^ o.y;
        float f = __uint_as_float((bits >> 9) | 0x3f800000u) - 1.0f;
        float uu = fmaxf(f + TINY, TINY);         // == f*(1-tiny)+tiny in f32
        float g = -logf(-logf(uu));
        sval[j] = la + g;
        sidx[j] = j;
        __syncthreads();
        for (int off = 64; off; off >>= 1) {
            if (j < off) {
                float v2 = sval[j + off]; int i2 = sidx[j + off];
                if (v2 > sval[j] || (v2 == sval[j] && i2 < sidx[j])) {
                    sval[j] = v2; sidx[j] = i2;
                }
            }
            __syncthreads();
        }
        if (j == 0) cols[k] = sidx[0];
        __syncthreads();
    }
    if (j == 0) {
        int row = nodes[b];
        float ws[KSAMP]; float s = 0.f;
#pragma unroll
        for (int k = 0; k < KSAMP; k++) {
            int c = cols[k];
            float w = weight[(size_t)row * SCOPE + c];
            ws[k] = w; s += w;
            frontier_next[b * KSAMP + k] = edge[(size_t)row * SCOPE + c];
        }
        float denom = s + 1e-9f;
#pragma unroll
        for (int k = 0; k < KSAMP; k++) adj[b * KSAMP + k] = ws[k] / denom;
    }
}

// ---------------- sparse aggregation: out[b,:] = sum_k adj[b,k] * X[row(b,k),:] --------
__global__ void aggregate_kernel(const float* __restrict__ X,
                                 const int* __restrict__ rowidx,
                                 const float* __restrict__ adj,
                                 float* __restrict__ out,
                                 int D, int ldx) {
    int b = blockIdx.x;
    __shared__ const float* rows[KSAMP];
    __shared__ float w[KSAMP];
    if (threadIdx.x < KSAMP) {
        int e = b * KSAMP + threadIdx.x;
        int r = rowidx ? rowidx[e] : e;
        rows[threadIdx.x] = X + (size_t)r * ldx;
        w[threadIdx.x] = adj[e];
    }
    __syncthreads();
    float2* orow = reinterpret_cast<float2*>(out + (size_t)b * D);
    int D2 = D >> 1;
    for (int d = threadIdx.x; d < D2; d += blockDim.x) {
        float2 s = make_float2(0.f, 0.f);
#pragma unroll
        for (int k = 0; k < KSAMP; k++) {
            float2 v = reinterpret_cast<const float2*>(rows[k])[d];
            s.x = fmaf(w[k], v.x, s.x);
            s.y = fmaf(w[k], v.y, s.y);
        }
        orow[d] = s;
    }
}

// ---------------- launch ----------------
extern "C" void kernel_launch(void* const* d_in, const int* in_sizes, int n_in,
                              void* d_out, int out_size) {
    const int*   ids     = (const int*)d_in[0];
    const float* feature = (const float*)d_in[1];
    const int*   edge    = (const int*)d_in[2];
    const float* weight  = (const float*)d_in[3];
    const float* sW      = (const float*)d_in[4];
    const float* sW2     = (const float*)d_in[5];
    const float* sa      = (const float*)d_in[6];
    const float* W1      = (const float*)d_in[7];
    const float* W2      = (const float*)d_in[8];
    float* out = (float*)d_out;

    float *pM, *pu, *pla, *pXa, *pX1, *pXb, *pA0, *pA1;
    int *pf1, *pf2;
    cudaGetSymbolAddress((void**)&pM,  d_M);
    cudaGetSymbolAddress((void**)&pu,  d_u);
    cudaGetSymbolAddress((void**)&pla, d_logatt);
    cudaGetSymbolAddress((void**)&pXa, d_Xa);
    cudaGetSymbolAddress((void**)&pX1, d_X1);
    cudaGetSymbolAddress((void**)&pXb, d_Xb);
    cudaGetSymbolAddress((void**)&pA0, d_adjL0);
    cudaGetSymbolAddress((void**)&pA1, d_adjL1);
    cudaGetSymbolAddress((void**)&pf1, d_front1);
    cudaGetSymbolAddress((void**)&pf2, d_front2);

    setup_kernel<<<1, 1>>>(sa);
    build_M_kernel<<<dim3(19, 19), 256>>>(sW, sW2);

    // ---- step i=0 (layer 1), n = 256, frontier = ids ----
    sgemm_kernel<<<dim3(10, 4), 256>>>(feature, ids, pM, pu,
                                       BATCH, INPUT_DIM, INPUT_DIM,
                                       INPUT_DIM, INPUT_DIM, INPUT_DIM, 0);
    att_kernel<<<BATCH, 256>>>(feature, edge, weight, ids, pu, pla);
    sample_kernel<<<BATCH, SCOPE>>>(pla, ids, edge, weight, BATCH, 0, pf1, pA1);

    // ---- step i=1 (layer 0), n = 2560, frontier = d_front1 ----
    sgemm_kernel<<<dim3(10, 40), 256>>>(feature, pf1, pM, pu,
                                        N1, INPUT_DIM, INPUT_DIM,
                                        INPUT_DIM, INPUT_DIM, INPUT_DIM, 0);
    att_kernel<<<N1, 256>>>(feature, edge, weight, pf1, pu, pla);
    sample_kernel<<<N1, SCOPE>>>(pla, pf1, edge, weight, N1, 2, pf2, pA0);

    // ---- aggregation: layer 0 ----
    aggregate_kernel<<<N1, 256>>>(feature, pf2, pA0, pXa, INPUT_DIM, INPUT_DIM);
    sgemm_kernel<<<dim3(4, 40), 256>>>(pXa, nullptr, W1, pX1,
                                       N1, HIDDEN_DIM, INPUT_DIM,
                                       INPUT_DIM, HIDDEN_DIM, HIDDEN_DIM, 1);
    // ---- aggregation: layer 1 ----
    aggregate_kernel<<<BATCH, 256>>>(pX1, nullptr, pA1, pXb, HIDDEN_DIM, HIDDEN_DIM);
    sgemm_kernel<<<dim3(1, 4), 256>>>(pXb, nullptr, W2, out,
                                      BATCH, OUTPUT_DIM, HIDDEN_DIM,
                                      HIDDEN_DIM, OUTPUT_DIM, OUTPUT_DIM, 0);
}

// round 2
// speedup vs baseline: 1.1053x; 1.1053x over previous
#include <cuda_runtime.h>
#include <cstdint>
#include <cstddef>

// ---------------- problem constants ----------------
#define NODE_NUM 232965
#define INPUT_DIM 602
#define HIDDEN_DIM 256
#define OUTPUT_DIM 41
#define BATCH 256
#define SCOPE 128
#define KSAMP 10
#define N1 2560      /* BATCH*KSAMP */
#define N2 25600     /* N1*KSAMP */

// ---------------- device scratch (static; no allocations) ----------------
__device__ float    d_M[INPUT_DIM * INPUT_DIM];       // a0*W W^T + a1*W2 W2^T
__device__ float    d_u[N1 * INPUT_DIM];              // projected src features
__device__ float    d_logatt[N1 * SCOPE];
__device__ int      d_front1[N1];
__device__ int      d_front2[N2];
__device__ float    d_adjL1[BATCH * KSAMP];           // adj_list[1]
__device__ float    d_adjL0[N1 * KSAMP];              // adj_list[0]
__device__ float    d_Xa[N1 * INPUT_DIM];
__device__ float    d_X1[N1 * HIDDEN_DIM];
__device__ float    d_Xb[BATCH * HIDDEN_DIM];
__device__ float    d_a[3];
__device__ unsigned d_keys[4];                        // sk1.{hi,lo}, sk2.{hi,lo}

// ---------------- threefry2x32 (JAX-exact) ----------------
__device__ __forceinline__ uint2 threefry(unsigned k0, unsigned k1,
                                          unsigned c0, unsigned c1) {
    unsigned ks2 = k0 ^ k1 ^ 0x1BD11BDAu;
    unsigned x0 = c0 + k0, x1 = c1 + k1;
#define TF_R(r) { x0 += x1; x1 = (x1 << (r)) | (x1 >> (32 - (r))); x1 ^= x0; }
    TF_R(13) TF_R(15) TF_R(26) TF_R(6)
    x0 += k1;  x1 += ks2 + 1u;
    TF_R(17) TF_R(29) TF_R(16) TF_R(24)
    x0 += ks2; x1 += k0 + 2u;
    TF_R(13) TF_R(15) TF_R(26) TF_R(6)
    x0 += k0;  x1 += k1 + 3u;
    TF_R(17) TF_R(29) TF_R(16) TF_R(24)
    x0 += k1;  x1 += ks2 + 4u;
    TF_R(13) TF_R(15) TF_R(26) TF_R(6)
    x0 += ks2; x1 += k0 + 5u;
#undef TF_R
    return make_uint2(x0, x1);
}

// ---------------- setup: softmax(a), key chain ----------------
__global__ void setup_kernel(const float* __restrict__ sa) {
    float v0 = sa[0], v1 = sa[1], v2 = sa[2];
    float m = fmaxf(v0, fmaxf(v1, v2));
    float e0 = expf(v0 - m), e1 = expf(v1 - m), e2 = expf(v2 - m);
    float s = e0 + e1 + e2;
    d_a[0] = e0 / s; d_a[1] = e1 / s; d_a[2] = e2 / s;
    // key(42) -> (0,42). partitionable split: child i = TF(key, 0, i)
    uint2 key1 = threefry(0u, 42u, 0u, 0u);
    uint2 sk1  = threefry(0u, 42u, 0u, 1u);
    uint2 sk2  = threefry(key1.x, key1.y, 0u, 1u);
    d_keys[0] = sk1.x; d_keys[1] = sk1.y;
    d_keys[2] = sk2.x; d_keys[3] = sk2.y;
}

// ---------------- M = a0 * Wa Wa^T + a1 * Wb Wb^T  (602x602, K=256) ----------------
__global__ void build_M_kernel(const float* __restrict__ Wa,
                               const float* __restrict__ Wb) {
    __shared__ float Fs[32][17];
    __shared__ float Gs[32][17];
    int f0 = blockIdx.y * 32, g0 = blockIdx.x * 32;
    int tid = threadIdx.x;
    int tx = tid & 15, ty = tid >> 4;
    float acc[2][2][2] = {};
    for (int p = 0; p < 2; p++) {
        const float* W = p ? Wb : Wa;
        for (int k0 = 0; k0 < HIDDEN_DIM; k0 += 16) {
#pragma unroll
            for (int e = 0; e < 2; e++) {
                int idx = tid + e * 256;      // 0..511
                int r = idx >> 4, c = idx & 15;
                Fs[r][c] = (f0 + r < INPUT_DIM) ? W[(size_t)(f0 + r) * HIDDEN_DIM + k0 + c] : 0.f;
                Gs[r][c] = (g0 + r < INPUT_DIM) ? W[(size_t)(g0 + r) * HIDDEN_DIM + k0 + c] : 0.f;
            }
            __syncthreads();
#pragma unroll
            for (int c = 0; c < 16; c++)
#pragma unroll
                for (int i = 0; i < 2; i++)
#pragma unroll
                    for (int j = 0; j < 2; j++)
                        acc[p][i][j] += Fs[ty * 2 + i][c] * Gs[tx * 2 + j][c];
            __syncthreads();
        }
    }
    float a0 = d_a[0], a1 = d_a[1];
#pragma unroll
    for (int i = 0; i < 2; i++)
#pragma unroll
        for (int j = 0; j < 2; j++) {
            int f = f0 + ty * 2 + i, g = g0 + tx * 2 + j;
            if (f < INPUT_DIM && g < INPUT_DIM)
                d_M[(size_t)f * INPUT_DIM + g] = a0 * acc[0][i][j] + a1 * acc[1][i][j];
        }
}

// ---------------- generic tiled SGEMM with optional row-gather + relu ----------------
// C[M,N] = gatherA(A)[M,K] @ B[K,N]
__global__ void sgemm_kernel(const float* __restrict__ A, const int* __restrict__ rowidx,
                             const float* __restrict__ B, float* __restrict__ C,
                             int M, int N, int K, int lda, int ldb, int ldc, int relu) {
    __shared__ float As[16][64];
    __shared__ float Bs[16][64];
    int tid = threadIdx.x;
    int row0 = blockIdx.y * 64, col0 = blockIdx.x * 64;
    int tx = tid & 15, ty = tid >> 4;
    int ar = tid >> 2;             // 0..63
    int ac = (tid & 3) * 4;        // 0,4,8,12
    int bk = tid >> 4;             // 0..15
    int bc = (tid & 15) * 4;
    int grow = row0 + ar;
    const float* Arow = nullptr;
    if (grow < M) {
        int r = rowidx ? rowidx[grow] : grow;
        Arow = A + (size_t)r * lda;
    }
    float acc[4][4] = {};
    for (int k0 = 0; k0 < K; k0 += 16) {
#pragma unroll
        for (int i = 0; i < 4; i++) {
            int k = k0 + ac + i;
            As[ac + i][ar] = (Arow != nullptr && k < K) ? Arow[k] : 0.f;
        }
        int kb = k0 + bk;
#pragma unroll
        for (int i = 0; i < 4; i++) {
            int c = col0 + bc + i;
            Bs[bk][bc + i] = (kb < K && c < N) ? B[(size_t)kb * ldb + c] : 0.f;
        }
        __syncthreads();
#pragma unroll
        for (int kk = 0; kk < 16; kk++) {
            float4 av = *reinterpret_cast<const float4*>(&As[kk][ty * 4]);
            float4 bv = *reinterpret_cast<const float4*>(&Bs[kk][tx * 4]);
            float a[4] = {av.x, av.y, av.z, av.w};
            float b[4] = {bv.x, bv.y, bv.z, bv.w};
#pragma unroll
            for (int i = 0; i < 4; i++)
#pragma unroll
                for (int j = 0; j < 4; j++)
                    acc[i][j] = fmaf(a[i], b[j], acc[i][j]);
        }
        __syncthreads();
    }
#pragma unroll
    for (int i = 0; i < 4; i++) {
        int r = row0 + ty * 4 + i;
        if (r >= M) continue;
#pragma unroll
        for (int j = 0; j < 4; j++) {
            int c = col0 + tx * 4 + j;
            if (c < N) {
                float v = acc[i][j];
                if (relu) v = fmaxf(v, 0.f);
                C[(size_t)r * ldc + c] = v;
            }
        }
    }
}

// ---------------- attention: logatt[n,s] = log(relu(u[n].t[n,s] + a2*w) + 1e-9) --------
// v2: 2 neighbor rows per warp per iteration, all loads batched up-front for MLP.
// Per-lane accumulation order identical (bitwise) to v1: ascending stride-32 float2
// chunks, fmaf chain, shfl_down tree.
__global__ __launch_bounds__(256, 3)
void att_kernel(const float* __restrict__ feature,
                const int* __restrict__ edge,
                const float* __restrict__ weight,
                const int* __restrict__ nodes,
                const float* __restrict__ u,
                float* __restrict__ logatt) {
    int b = blockIdx.x;
    __shared__ float2 us2[INPUT_DIM / 2];     // 301
    int row = nodes[b];
    const float2* urow = reinterpret_cast<const float2*>(u + (size_t)b * INPUT_DIM);
    for (int i = threadIdx.x; i < INPUT_DIM / 2; i += blockDim.x) us2[i] = urow[i];
    __syncthreads();
    float a2 = d_a[2];
    int warp = threadIdx.x >> 5, lane = threadIdx.x & 31;
    const int* erow = edge + (size_t)row * SCOPE;
    const float* wrow = weight + (size_t)row * SCOPE;
    const bool has = lane < (INPUT_DIM / 2 - 288);   // lane < 13
#pragma unroll 1
    for (int i = 0; i < 16; i += 2) {
        int s0 = warp * 16 + i;
        int nb0 = erow[s0], nb1 = erow[s0 + 1];
        const float2* p0 = reinterpret_cast<const float2*>(feature + (size_t)nb0 * INPUT_DIM);
        const float2* p1 = reinterpret_cast<const float2*>(feature + (size_t)nb1 * INPUT_DIM);
        float2 v0[10], v1[10];
#pragma unroll
        for (int t = 0; t < 9; t++) {
            v0[t] = __ldg(p0 + lane + 32 * t);
            v1[t] = __ldg(p1 + lane + 32 * t);
        }
        if (has) {
            v0[9] = __ldg(p0 + lane + 288);
            v1[9] = __ldg(p1 + lane + 288);
        }
        float acc0 = 0.f, acc1 = 0.f;
#pragma unroll
        for (int t = 0; t < 9; t++) {
            float2 uv = us2[lane + 32 * t];
            acc0 = fmaf(uv.x, v0[t].x, acc0);
            acc0 = fmaf(uv.y, v0[t].y, acc0);
            acc1 = fmaf(uv.x, v1[t].x, acc1);
            acc1 = fmaf(uv.y, v1[t].y, acc1);
        }
        if (has) {
            float2 uv = us2[lane + 288];
            acc0 = fmaf(uv.x, v0[9].x, acc0);
            acc0 = fmaf(uv.y, v0[9].y, acc0);
            acc1 = fmaf(uv.x, v1[9].x, acc1);
            acc1 = fmaf(uv.y, v1[9].y, acc1);
        }
#pragma unroll
        for (int o = 16; o; o >>= 1) {
            acc0 += __shfl_down_sync(0xffffffffu, acc0, o);
            acc1 += __shfl_down_sync(0xffffffffu, acc1, o);
        }
        if (lane == 0) {
            float att0 = fmaxf(acc0 + a2 * wrow[s0], 0.f) + 1e-9f;
            float att1 = fmaxf(acc1 + a2 * wrow[s0 + 1], 0.f) + 1e-9f;
            logatt[(size_t)b * SCOPE + s0]     = logf(att0);
            logatt[(size_t)b * SCOPE + s0 + 1] = logf(att1);
        }
    }
}

// ---------------- gumbel-max sampling (JAX categorical, partitionable threefry) --------
// v2: one warp per k-sample, register argmax + shuffle reduce (2 barriers total).
__global__ void sample_kernel(const float* __restrict__ logatt,
                              const int* __restrict__ nodes,
                              const int* __restrict__ edge,
                              const float* __restrict__ weight,
                              int n, int key_off,
                              int* __restrict__ frontier_next,
                              float* __restrict__ adj) {
    int b = blockIdx.x;
    int tid = threadIdx.x;             // 128 threads = SCOPE
    int warp = tid >> 5, lane = tid & 31;
    __shared__ float la[SCOPE];
    __shared__ int   cols[KSAMP];
    la[tid] = logatt[(size_t)b * SCOPE + tid];
    __syncthreads();
    unsigned k0 = d_keys[key_off], k1 = d_keys[key_off + 1];
    const float TINY = 1.1754943508222875e-38f;
    for (int k = warp; k < KSAMP; k += 4) {
        float best; int bidx;
#pragma unroll
        for (int t = 0; t < 4; t++) {
            int j = lane + 32 * t;
            // counter = linear index into gumbel tensor of shape (KSAMP, n, SCOPE)
            unsigned p = ((unsigned)(k * n + b)) * SCOPE + (unsigned)j;
            uint2 o = threefry(k0, k1, 0u, p);
            unsigned bits = o.x ^ o.y;
            float f = __uint_as_float((bits >> 9) | 0x3f800000u) - 1.0f;
            float uu = fmaxf(f + TINY, TINY);
            float g = -logf(-logf(uu));
            float v = la[j] + g;
            if (t == 0) { best = v; bidx = j; }
            else if (v > best) { best = v; bidx = j; }   // strict > keeps first max
        }
#pragma unroll
        for (int o2 = 16; o2; o2 >>= 1) {
            float v2 = __shfl_down_sync(0xffffffffu, best, o2);
            int   i2 = __shfl_down_sync(0xffffffffu, bidx, o2);
            if (v2 > best || (v2 == best && i2 < bidx)) { best = v2; bidx = i2; }
        }
        if (lane == 0) cols[k] = bidx;
    }
    __syncthreads();
    if (tid == 0) {
        int row = nodes[b];
        float ws[KSAMP]; float s = 0.f;
#pragma unroll
        for (int k = 0; k < KSAMP; k++) {
            int c = cols[k];
            float w = weight[(size_t)row * SCOPE + c];
            ws[k] = w; s += w;
            frontier_next[b * KSAMP + k] = edge[(size_t)row * SCOPE + c];
        }
        float denom = s + 1e-9f;
#pragma unroll
        for (int k = 0; k < KSAMP; k++) adj[b * KSAMP + k] = ws[k] / denom;
    }
}

// ---------------- sparse aggregation: out[b,:] = sum_k adj[b,k] * X[row(b,k),:] --------
__global__ void aggregate_kernel(const float* __restrict__ X,
                                 const int* __restrict__ rowidx,
                                 const float* __restrict__ adj,
                                 float* __restrict__ out,
                                 int D, int ldx) {
    int b = blockIdx.x;
    __shared__ const float* rows[KSAMP];
    __shared__ float w[KSAMP];
    if (threadIdx.x < KSAMP) {
        int e = b * KSAMP + threadIdx.x;
        int r = rowidx ? rowidx[e] : e;
        rows[threadIdx.x] = X + (size_t)r * ldx;
        w[threadIdx.x] = adj[e];
    }
    __syncthreads();
    float2* orow = reinterpret_cast<float2*>(out + (size_t)b * D);
    int D2 = D >> 1;
    for (int d = threadIdx.x; d < D2; d += blockDim.x) {
        float2 s = make_float2(0.f, 0.f);
#pragma unroll
        for (int k = 0; k < KSAMP; k++) {
            float2 v = reinterpret_cast<const float2*>(rows[k])[d];
            s.x = fmaf(w[k], v.x, s.x);
            s.y = fmaf(w[k], v.y, s.y);
        }
        orow[d] = s;
    }
}

// ---------------- launch ----------------
extern "C" void kernel_launch(void* const* d_in, const int* in_sizes, int n_in,
                              void* d_out, int out_size) {
    const int*   ids     = (const int*)d_in[0];
    const float* feature = (const float*)d_in[1];
    const int*   edge    = (const int*)d_in[2];
    const float* weight  = (const float*)d_in[3];
    const float* sW      = (const float*)d_in[4];
    const float* sW2     = (const float*)d_in[5];
    const float* sa      = (const float*)d_in[6];
    const float* W1      = (const float*)d_in[7];
    const float* W2      = (const float*)d_in[8];
    float* out = (float*)d_out;

    float *pM, *pu, *pla, *pXa, *pX1, *pXb, *pA0, *pA1;
    int *pf1, *pf2;
    cudaGetSymbolAddress((void**)&pM,  d_M);
    cudaGetSymbolAddress((void**)&pu,  d_u);
    cudaGetSymbolAddress((void**)&pla, d_logatt);
    cudaGetSymbolAddress((void**)&pXa, d_Xa);
    cudaGetSymbolAddress((void**)&pX1, d_X1);
    cudaGetSymbolAddress((void**)&pXb, d_Xb);
    cudaGetSymbolAddress((void**)&pA0, d_adjL0);
    cudaGetSymbolAddress((void**)&pA1, d_adjL1);
    cudaGetSymbolAddress((void**)&pf1, d_front1);
    cudaGetSymbolAddress((void**)&pf2, d_front2);

    setup_kernel<<<1, 1>>>(sa);
    build_M_kernel<<<dim3(19, 19), 256>>>(sW, sW2);

    // ---- step i=0 (layer 1), n = 256, frontier = ids ----
    sgemm_kernel<<<dim3(10, 4), 256>>>(feature, ids, pM, pu,
                                       BATCH, INPUT_DIM, INPUT_DIM,
                                       INPUT_DIM, INPUT_DIM, INPUT_DIM, 0);
    att_kernel<<<BATCH, 256>>>(feature, edge, weight, ids, pu, pla);
    sample_kernel<<<BATCH, SCOPE>>>(pla, ids, edge, weight, BATCH, 0, pf1, pA1);

    // ---- step i=1 (layer 0), n = 2560, frontier = d_front1 ----
    sgemm_kernel<<<dim3(10, 40), 256>>>(feature, pf1, pM, pu,
                                        N1, INPUT_DIM, INPUT_DIM,
                                        INPUT_DIM, INPUT_DIM, INPUT_DIM, 0);
    att_kernel<<<N1, 256>>>(feature, edge, weight, pf1, pu, pla);
    sample_kernel<<<N1, SCOPE>>>(pla, pf1, edge, weight, N1, 2, pf2, pA0);

    // ---- aggregation: layer 0 ----
    aggregate_kernel<<<N1, 256>>>(feature, pf2, pA0, pXa, INPUT_DIM, INPUT_DIM);
    sgemm_kernel<<<dim3(4, 40), 256>>>(pXa, nullptr, W1, pX1,
                                       N1, HIDDEN_DIM, INPUT_DIM,
                                       INPUT_DIM, HIDDEN_DIM, HIDDEN_DIM, 1);
    // ---- aggregation: layer 1 ----
    aggregate_kernel<<<BATCH, 256>>>(pX1, nullptr, pA1, pXb, HIDDEN_DIM, HIDDEN_DIM);
    sgemm_kernel<<<dim3(1, 4), 256>>>(pXb, nullptr, W2, out,
                                      BATCH, OUTPUT_DIM, HIDDEN_DIM,
                                      HIDDEN_DIM, OUTPUT_DIM, OUTPUT_DIM, 0);
}

// round 4
// speedup vs baseline: 1.1946x; 1.0807x over previous
#include <cuda_runtime.h>
#include <cstdint>
#include <cstddef>

// ---------------- problem constants ----------------
#define NODE_NUM 232965
#define INPUT_DIM 602
#define HIDDEN_DIM 256
#define OUTPUT_DIM 41
#define BATCH 256
#define SCOPE 128
#define KSAMP 10
#define N1 2560      /* BATCH*KSAMP */
#define N2 25600     /* N1*KSAMP */
#define KCAT 512     /* 2*HIDDEN_DIM */

// ---------------- device scratch (static; no allocations) ----------------
__device__ float    d_M[INPUT_DIM * INPUT_DIM];       // a0*W W^T + a1*W2 W2^T
__device__ float    d_Wcat[INPUT_DIM * KCAT];         // [a0*W | a1*W2]
__device__ float    d_Wt[KCAT * INPUT_DIM];           // [W ; W2]^T (unscaled)
__device__ float    d_u[N1 * INPUT_DIM];              // projected src features
__device__ int      d_front1[N1];
__device__ int      d_front2[N2];
__device__ float    d_adjL1[BATCH * KSAMP];           // adj_list[1]
__device__ float    d_adjL0[N1 * KSAMP];              // adj_list[0]
__device__ float    d_Xa[N1 * INPUT_DIM];
__device__ float    d_X1[N1 * HIDDEN_DIM];
__device__ float    d_Xb[BATCH * HIDDEN_DIM];
__device__ float    d_a[3];
__device__ unsigned d_keys[4];                        // sk1.{hi,lo}, sk2.{hi,lo}

// ---------------- threefry2x32 (JAX-exact) ----------------
__device__ __forceinline__ uint2 threefry(unsigned k0, unsigned k1,
                                          unsigned c0, unsigned c1) {
    unsigned ks2 = k0 ^ k1 ^ 0x1BD11BDAu;
    unsigned x0 = c0 + k0, x1 = c1 + k1;
#define TF_R(r) { x0 += x1; x1 = (x1 << (r)) | (x1 >> (32 - (r))); x1 ^= x0; }
    TF_R(13) TF_R(15) TF_R(26) TF_R(6)
    x0 += k1;  x1 += ks2 + 1u;
    TF_R(17) TF_R(29) TF_R(16) TF_R(24)
    x0 += ks2; x1 += k0 + 2u;
    TF_R(13) TF_R(15) TF_R(26) TF_R(6)
    x0 += k0;  x1 += k1 + 3u;
    TF_R(17) TF_R(29) TF_R(16) TF_R(24)
    x0 += k1;  x1 += ks2 + 4u;
    TF_R(13) TF_R(15) TF_R(26) TF_R(6)
    x0 += ks2; x1 += k0 + 5u;
#undef TF_R
    return make_uint2(x0, x1);
}

// ---------------- setup: softmax(a), key chain ----------------
__global__ void setup_kernel(const float* __restrict__ sa) {
    float v0 = sa[0], v1 = sa[1], v2 = sa[2];
    float m = fmaxf(v0, fmaxf(v1, v2));
    float e0 = expf(v0 - m), e1 = expf(v1 - m), e2 = expf(v2 - m);
    float s = e0 + e1 + e2;
    d_a[0] = e0 / s; d_a[1] = e1 / s; d_a[2] = e2 / s;
    // key(42) -> (0,42). partitionable split: child i = TF(key, 0, i)
    uint2 key1 = threefry(0u, 42u, 0u, 0u);
    uint2 sk1  = threefry(0u, 42u, 0u, 1u);
    uint2 sk2  = threefry(key1.x, key1.y, 0u, 1u);
    d_keys[0] = sk1.x; d_keys[1] = sk1.y;
    d_keys[2] = sk2.x; d_keys[3] = sk2.y;
}

// ---------------- prep: Wcat[f][k] = a{0,1}*W{1,2}[f][k'], Wt[k][f] = W{1,2}[f][k'] ----
__global__ void prep_kernel(const float* __restrict__ W, const float* __restrict__ W2) {
    int f = blockIdx.x;
    float a0 = d_a[0], a1 = d_a[1];
    for (int k = threadIdx.x; k < KCAT; k += blockDim.x) {
        float v  = (k < HIDDEN_DIM) ? W[(size_t)f * HIDDEN_DIM + k]
                                    : W2[(size_t)f * HIDDEN_DIM + (k - HIDDEN_DIM)];
        float sc = (k < HIDDEN_DIM) ? a0 : a1;
        d_Wcat[(size_t)f * KCAT + k] = v * sc;
        d_Wt[(size_t)k * INPUT_DIM + f] = v;
    }
}

// ---------------- fast SGEMM: C[M,N] = gatherA(A)[M,K] @ B[K,N] ----------------
// BM=128, BN=64, BK=16, 256 threads, 8x4 per thread, double-buffered.
__global__ __launch_bounds__(256, 2)
void sgemm_kernel(const float* __restrict__ A, const int* __restrict__ rowidx,
                  const float* __restrict__ B, float* __restrict__ C,
                  int M, int N, int K, int lda, int ldb, int ldc, int relu) {
    __shared__ float As[2][16][132];
    __shared__ float Bs[2][16][64];
    __shared__ const float* rowp[128];
    int tid = threadIdx.x;
    int row0 = blockIdx.y * 128, col0 = blockIdx.x * 64;

    if (tid < 128) {
        int grow = row0 + tid;
        const float* p = nullptr;
        if (grow < M) {
            int r = rowidx ? rowidx[grow] : grow;
            p = A + (size_t)r * lda;
        }
        rowp[tid] = p;
    }
    __syncthreads();

    int am  = tid >> 3;     // 0..31, +32*i
    int ac2 = tid & 7;      // float2 column within k-tile
    int bkb = tid >> 6;     // 0..3, +4*i
    int bc  = tid & 63;

    int ty = tid >> 4, tx = tid & 15;
    float acc[8][4] = {};
    float2 areg[4];
    float  breg[4];

    int tiles = (K + 15) >> 4;

    // prologue: tile 0
    {
        int k0 = 0;
#pragma unroll
        for (int i = 0; i < 4; i++) {
            const float* p = rowp[am + 32 * i];
            int kc = k0 + ac2 * 2;
            areg[i] = (p != nullptr && kc < K)
                    ? *reinterpret_cast<const float2*>(p + kc) : make_float2(0.f, 0.f);
        }
#pragma unroll
        for (int i = 0; i < 4; i++) {
            int kk = k0 + bkb + 4 * i, c = col0 + bc;
            breg[i] = (kk < K && c < N) ? B[(size_t)kk * ldb + c] : 0.f;
        }
#pragma unroll
        for (int i = 0; i < 4; i++) {
            As[0][ac2 * 2][am + 32 * i]     = areg[i].x;
            As[0][ac2 * 2 + 1][am + 32 * i] = areg[i].y;
        }
#pragma unroll
        for (int i = 0; i < 4; i++) Bs[0][bkb + 4 * i][bc] = breg[i];
    }
    __syncthreads();

    for (int t = 0; t < tiles; t++) {
        int buf = t & 1;
        bool more = (t + 1 < tiles);
        if (more) {
            int k0 = (t + 1) << 4;
#pragma unroll
            for (int i = 0; i < 4; i++) {
                const float* p = rowp[am + 32 * i];
                int kc = k0 + ac2 * 2;
                areg[i] = (p != nullptr && kc < K)
                        ? *reinterpret_cast<const float2*>(p + kc) : make_float2(0.f, 0.f);
            }
#pragma unroll
            for (int i = 0; i < 4; i++) {
                int kk = k0 + bkb + 4 * i, c = col0 + bc;
                breg[i] = (kk < K && c < N) ? B[(size_t)kk * ldb + c] : 0.f;
            }
        }
#pragma unroll
        for (int kk = 0; kk < 16; kk++) {
            float4 a0v = *reinterpret_cast<const float4*>(&As[buf][kk][ty * 8]);
            float4 a1v = *reinterpret_cast<const float4*>(&As[buf][kk][ty * 8 + 4]);
            float4 bv  = *reinterpret_cast<const float4*>(&Bs[buf][kk][tx * 4]);
            float av[8] = {a0v.x, a0v.y, a0v.z, a0v.w, a1v.x, a1v.y, a1v.z, a1v.w};
            float bb[4] = {bv.x, bv.y, bv.z, bv.w};
#pragma unroll
            for (int i = 0; i < 8; i++)
#pragma unroll
                for (int j = 0; j < 4; j++)
                    acc[i][j] = fmaf(av[i], bb[j], acc[i][j]);
        }
        if (more) {
            int nb = 1 - buf;
#pragma unroll
            for (int i = 0; i < 4; i++) {
                As[nb][ac2 * 2][am + 32 * i]     = areg[i].x;
                As[nb][ac2 * 2 + 1][am + 32 * i] = areg[i].y;
            }
#pragma unroll
            for (int i = 0; i < 4; i++) Bs[nb][bkb + 4 * i][bc] = breg[i];
        }
        __syncthreads();
    }

#pragma unroll
    for (int i = 0; i < 8; i++) {
        int r = row0 + ty * 8 + i;
        if (r >= M) continue;
#pragma unroll
        for (int j = 0; j < 4; j++) {
            int c = col0 + tx * 4 + j;
            if (c < N) {
                float v = acc[i][j];
                if (relu) v = fmaxf(v, 0.f);
                C[(size_t)r * ldc + c] = v;
            }
        }
    }
}

// ---------------- fused attention + gumbel-max sampling ----------------
// att math bitwise-identical to round-2 att_kernel; sampling identical to round-2
// sample_kernel (smem la values are the same floats).
__global__ __launch_bounds__(256, 3)
void attsample_kernel(const float* __restrict__ feature,
                      const int* __restrict__ edge,
                      const float* __restrict__ weight,
                      const int* __restrict__ nodes,
                      const float* __restrict__ u,
                      int n, int key_off,
                      int* __restrict__ frontier_next,
                      float* __restrict__ adj) {
    int b = blockIdx.x;
    __shared__ float2 us2[INPUT_DIM / 2];     // 301
    __shared__ float  la[SCOPE];
    __shared__ int    cols[KSAMP];
    int row = nodes[b];
    const float2* urow = reinterpret_cast<const float2*>(u + (size_t)b * INPUT_DIM);
    for (int i = threadIdx.x; i < INPUT_DIM / 2; i += blockDim.x) us2[i] = urow[i];
    __syncthreads();
    float a2 = d_a[2];
    int warp = threadIdx.x >> 5, lane = threadIdx.x & 31;
    const int* erow = edge + (size_t)row * SCOPE;
    const float* wrow = weight + (size_t)row * SCOPE;
    const bool has = lane < (INPUT_DIM / 2 - 288);   // lane < 13
#pragma unroll 1
    for (int i = 0; i < 16; i += 2) {
        int s0 = warp * 16 + i;
        int nb0 = erow[s0], nb1 = erow[s0 + 1];
        const float2* p0 = reinterpret_cast<const float2*>(feature + (size_t)nb0 * INPUT_DIM);
        const float2* p1 = reinterpret_cast<const float2*>(feature + (size_t)nb1 * INPUT_DIM);
        float2 v0[10], v1[10];
#pragma unroll
        for (int t = 0; t < 9; t++) {
            v0[t] = __ldg(p0 + lane + 32 * t);
            v1[t] = __ldg(p1 + lane + 32 * t);
        }
        if (has) {
            v0[9] = __ldg(p0 + lane + 288);
            v1[9] = __ldg(p1 + lane + 288);
        }
        float acc0 = 0.f, acc1 = 0.f;
#pragma unroll
        for (int t = 0; t < 9; t++) {
            float2 uv = us2[lane + 32 * t];
            acc0 = fmaf(uv.x, v0[t].x, acc0);
            acc0 = fmaf(uv.y, v0[t].y, acc0);
            acc1 = fmaf(uv.x, v1[t].x, acc1);
            acc1 = fmaf(uv.y, v1[t].y, acc1);
        }
        if (has) {
            float2 uv = us2[lane + 288];
            acc0 = fmaf(uv.x, v0[9].x, acc0);
            acc0 = fmaf(uv.y, v0[9].y, acc0);
            acc1 = fmaf(uv.x, v1[9].x, acc1);
            acc1 = fmaf(uv.y, v1[9].y, acc1);
        }
#pragma unroll
        for (int o = 16; o; o >>= 1) {
            acc0 += __shfl_down_sync(0xffffffffu, acc0, o);
            acc1 += __shfl_down_sync(0xffffffffu, acc1, o);
        }
        if (lane == 0) {
            la[s0]     = logf(fmaxf(acc0 + a2 * wrow[s0],     0.f) + 1e-9f);
            la[s0 + 1] = logf(fmaxf(acc1 + a2 * wrow[s0 + 1], 0.f) + 1e-9f);
        }
    }
    __syncthreads();

    unsigned k0 = d_keys[key_off], k1 = d_keys[key_off + 1];
    const float TINY = 1.1754943508222875e-38f;
    for (int k = warp; k < KSAMP; k += 8) {
        float best; int bidx;
#pragma unroll
        for (int t = 0; t < 4; t++) {
            int j = lane + 32 * t;
            // counter = linear index into gumbel tensor of shape (KSAMP, n, SCOPE)
            unsigned p = ((unsigned)(k * n + b)) * SCOPE + (unsigned)j;
            uint2 o = threefry(k0, k1, 0u, p);
            unsigned bits = o.x ^ o.y;
            float f = __uint_as_float((bits >> 9) | 0x3f800000u) - 1.0f;
            float uu = fmaxf(f + TINY, TINY);
            float g = -logf(-logf(uu));
            float v = la[j] + g;
            if (t == 0) { best = v; bidx = j; }
            else if (v > best) { best = v; bidx = j; }   // strict > keeps first max
        }
#pragma unroll
        for (int o2 = 16; o2; o2 >>= 1) {
            float v2 = __shfl_down_sync(0xffffffffu, best, o2);
            int   i2 = __shfl_down_sync(0xffffffffu, bidx, o2);
            if (v2 > best || (v2 == best && i2 < bidx)) { best = v2; bidx = i2; }
        }
        if (lane == 0) cols[k] = bidx;
    }
    __syncthreads();
    if (threadIdx.x == 0) {
        float ws[KSAMP]; float s = 0.f;
#pragma unroll
        for (int k = 0; k < KSAMP; k++) {
            int c = cols[k];
            float w = wrow[c];
            ws[k] = w; s += w;
            frontier_next[b * KSAMP + k] = erow[c];
        }
        float denom = s + 1e-9f;
#pragma unroll
        for (int k = 0; k < KSAMP; k++) adj[b * KSAMP + k] = ws[k] / denom;
    }
}

// ---------------- sparse aggregation: out[b,:] = sum_k adj[b,k] * X[row(b,k),:] --------
__global__ void aggregate_kernel(const float* __restrict__ X,
                                 const int* __restrict__ rowidx,
                                 const float* __restrict__ adj,
                                 float* __restrict__ out,
                                 int D, int ldx) {
    int b = blockIdx.x;
    __shared__ const float* rows[KSAMP];
    __shared__ float w[KSAMP];
    if (threadIdx.x < KSAMP) {
        int e = b * KSAMP + threadIdx.x;
        int r = rowidx ? rowidx[e] : e;
        rows[threadIdx.x] = X + (size_t)r * ldx;
        w[threadIdx.x] = adj[e];
    }
    __syncthreads();
    float2* orow = reinterpret_cast<float2*>(out + (size_t)b * D);
    int D2 = D >> 1;
    for (int d = threadIdx.x; d < D2; d += blockDim.x) {
        float2 s = make_float2(0.f, 0.f);
#pragma unroll
        for (int k = 0; k < KSAMP; k++) {
            float2 v = reinterpret_cast<const float2*>(rows[k])[d];
            s.x = fmaf(w[k], v.x, s.x);
            s.y = fmaf(w[k], v.y, s.y);
        }
        orow[d] = s;
    }
}

// ---------------- launch ----------------
static inline dim3 gemm_grid(int M, int N) {
    return dim3((N + 63) / 64, (M + 127) / 128);
}

extern "C" void kernel_launch(void* const* d_in, const int* in_sizes, int n_in,
                              void* d_out, int out_size) {
    const int*   ids     = (const int*)d_in[0];
    const float* feature = (const float*)d_in[1];
    const int*   edge    = (const int*)d_in[2];
    const float* weight  = (const float*)d_in[3];
    const float* sW      = (const float*)d_in[4];
    const float* sW2     = (const float*)d_in[5];
    const float* sa      = (const float*)d_in[6];
    const float* W1      = (const float*)d_in[7];
    const float* W2      = (const float*)d_in[8];
    float* out = (float*)d_out;

    float *pM, *pWcat, *pWt, *pu, *pXa, *pX1, *pXb, *pA0, *pA1;
    int *pf1, *pf2;
    cudaGetSymbolAddress((void**)&pM,    d_M);
    cudaGetSymbolAddress((void**)&pWcat, d_Wcat);
    cudaGetSymbolAddress((void**)&pWt,   d_Wt);
    cudaGetSymbolAddress((void**)&pu,    d_u);
    cudaGetSymbolAddress((void**)&pXa,   d_Xa);
    cudaGetSymbolAddress((void**)&pX1,   d_X1);
    cudaGetSymbolAddress((void**)&pXb,   d_Xb);
    cudaGetSymbolAddress((void**)&pA0,   d_adjL0);
    cudaGetSymbolAddress((void**)&pA1,   d_adjL1);
    cudaGetSymbolAddress((void**)&pf1,   d_front1);
    cudaGetSymbolAddress((void**)&pf2,   d_front2);

    setup_kernel<<<1, 1>>>(sa);
    prep_kernel<<<INPUT_DIM, 256>>>(sW, sW2);

    // M = Wcat @ Wt   (602 x 602, K=512)
    sgemm_kernel<<<gemm_grid(INPUT_DIM, INPUT_DIM), 256>>>(
        pWcat, nullptr, pWt, pM,
        INPUT_DIM, INPUT_DIM, KCAT, KCAT, INPUT_DIM, INPUT_DIM, 0);

    // ---- step i=0 (layer 1), n = 256, frontier = ids ----
    sgemm_kernel<<<gemm_grid(BATCH, INPUT_DIM), 256>>>(
        feature, ids, pM, pu,
        BATCH, INPUT_DIM, INPUT_DIM, INPUT_DIM, INPUT_DIM, INPUT_DIM, 0);
    attsample_kernel<<<BATCH, 256>>>(feature, edge, weight, ids, pu,
                                     BATCH, 0, pf1, pA1);

    // ---- step i=1 (layer 0), n = 2560, frontier = d_front1 ----
    sgemm_kernel<<<gemm_grid(N1, INPUT_DIM), 256>>>(
        feature, pf1, pM, pu,
        N1, INPUT_DIM, INPUT_DIM, INPUT_DIM, INPUT_DIM, INPUT_DIM, 0);
    attsample_kernel<<<N1, 256>>>(feature, edge, weight, pf1, pu,
                                  N1, 2, pf2, pA0);

    // ---- aggregation: layer 0 ----
    aggregate_kernel<<<N1, 256>>>(feature, pf2, pA0, pXa, INPUT_DIM, INPUT_DIM);
    sgemm_kernel<<<gemm_grid(N1, HIDDEN_DIM), 256>>>(
        pXa, nullptr, W1, pX1,
        N1, HIDDEN_DIM, INPUT_DIM, INPUT_DIM, HIDDEN_DIM, HIDDEN_DIM, 1);

    // ---- aggregation: layer 1 ----
    aggregate_kernel<<<BATCH, 256>>>(pX1, nullptr, pA1, pXb, HIDDEN_DIM, HIDDEN_DIM);
    sgemm_kernel<<<gemm_grid(BATCH, OUTPUT_DIM), 256>>>(
        pXb, nullptr, W2, out,
        BATCH, OUTPUT_DIM, HIDDEN_DIM, HIDDEN_DIM, OUTPUT_DIM, OUTPUT_DIM, 0);
}

// round 5
// speedup vs baseline: 1.3691x; 1.1461x over previous
#include <cuda_runtime.h>
#include <cstdint>
#include <cstddef>

// ---------------- problem constants ----------------
#define NODE_NUM 232965
#define INPUT_DIM 602
#define HIDDEN_DIM 256
#define OUTPUT_DIM 41
#define BATCH 256
#define SCOPE 128
#define KSAMP 10
#define N1 2560      /* BATCH*KSAMP */
#define N2 25600     /* N1*KSAMP */
#define KCAT 512     /* 2*HIDDEN_DIM */

// ---------------- device scratch (static; no allocations) ----------------
__device__ float    d_M[INPUT_DIM * INPUT_DIM];       // a0*W W^T + a1*W2 W2^T
__device__ float    d_Wcat[INPUT_DIM * KCAT];         // [a0*W | a1*W2]
__device__ float    d_Wt[KCAT * INPUT_DIM];           // [W ; W2]^T (unscaled)
__device__ float    d_u[N1 * INPUT_DIM];              // projected src features
__device__ float    d_part[1500000];                  // split-K partials (max 1.45M floats)
__device__ int      d_front1[N1];
__device__ int      d_front2[N2];
__device__ float    d_adjL1[BATCH * KSAMP];           // adj_list[1]
__device__ float    d_adjL0[N1 * KSAMP];              // adj_list[0]
__device__ float    d_Xa[N1 * INPUT_DIM];
__device__ float    d_X1[N1 * HIDDEN_DIM];
__device__ float    d_Xb[BATCH * HIDDEN_DIM];
__device__ float    d_a[3];
__device__ unsigned d_keys[4];                        // sk1.{hi,lo}, sk2.{hi,lo}

// ---------------- threefry2x32 (JAX-exact) ----------------
__device__ __forceinline__ uint2 threefry(unsigned k0, unsigned k1,
                                          unsigned c0, unsigned c1) {
    unsigned ks2 = k0 ^ k1 ^ 0x1BD11BDAu;
    unsigned x0 = c0 + k0, x1 = c1 + k1;
#define TF_R(r) { x0 += x1; x1 = (x1 << (r)) | (x1 >> (32 - (r))); x1 ^= x0; }
    TF_R(13) TF_R(15) TF_R(26) TF_R(6)
    x0 += k1;  x1 += ks2 + 1u;
    TF_R(17) TF_R(29) TF_R(16) TF_R(24)
    x0 += ks2; x1 += k0 + 2u;
    TF_R(13) TF_R(15) TF_R(26) TF_R(6)
    x0 += k0;  x1 += k1 + 3u;
    TF_R(17) TF_R(29) TF_R(16) TF_R(24)
    x0 += k1;  x1 += ks2 + 4u;
    TF_R(13) TF_R(15) TF_R(26) TF_R(6)
    x0 += ks2; x1 += k0 + 5u;
#undef TF_R
    return make_uint2(x0, x1);
}

// ---------------- setup: softmax(a), key chain ----------------
__global__ void setup_kernel(const float* __restrict__ sa) {
    float v0 = sa[0], v1 = sa[1], v2 = sa[2];
    float m = fmaxf(v0, fmaxf(v1, v2));
    float e0 = expf(v0 - m), e1 = expf(v1 - m), e2 = expf(v2 - m);
    float s = e0 + e1 + e2;
    d_a[0] = e0 / s; d_a[1] = e1 / s; d_a[2] = e2 / s;
    // key(42) -> (0,42). partitionable split: child i = TF(key, 0, i)
    uint2 key1 = threefry(0u, 42u, 0u, 0u);
    uint2 sk1  = threefry(0u, 42u, 0u, 1u);
    uint2 sk2  = threefry(key1.x, key1.y, 0u, 1u);
    d_keys[0] = sk1.x; d_keys[1] = sk1.y;
    d_keys[2] = sk2.x; d_keys[3] = sk2.y;
}

// ---------------- prep: Wcat[f][k] = a{0,1}*W{1,2}[f][k'], Wt[k][f] = W{1,2}[f][k'] ----
__global__ void prep_kernel(const float* __restrict__ W, const float* __restrict__ W2) {
    int f = blockIdx.x;
    float a0 = d_a[0], a1 = d_a[1];
    for (int k = threadIdx.x; k < KCAT; k += blockDim.x) {
        float v  = (k < HIDDEN_DIM) ? W[(size_t)f * HIDDEN_DIM + k]
                                    : W2[(size_t)f * HIDDEN_DIM + (k - HIDDEN_DIM)];
        float sc = (k < HIDDEN_DIM) ? a0 : a1;
        d_Wcat[(size_t)f * KCAT + k] = v * sc;
        d_Wt[(size_t)k * INPUT_DIM + f] = v;
    }
}

// ---------------- fast SGEMM with split-K: C = gatherA(A)[M,K] @ B[K,N] ----------------
// BM=128, BN=64, BK=16, 256 threads, 8x4 per thread, double-buffered.
// gridDim.z = S splits; split z covers K range [z*chunk, min(K,(z+1)*chunk)).
// S>1: writes partials (no relu) to C + z*M*ldc; S==1: writes final with relu.
__global__ __launch_bounds__(256, 2)
void sgemm_kernel(const float* __restrict__ A, const int* __restrict__ rowidx,
                  const float* __restrict__ B, float* __restrict__ C,
                  int M, int N, int K, int lda, int ldb, int ldc,
                  int relu, int chunk) {
    __shared__ float As[2][16][132];
    __shared__ float Bs[2][16][64];
    __shared__ const float* rowp[128];
    int tid = threadIdx.x;
    int row0 = blockIdx.y * 128, col0 = blockIdx.x * 64;
    int kbeg = blockIdx.z * chunk;
    int kend = min(K, kbeg + chunk);

    if (tid < 128) {
        int grow = row0 + tid;
        const float* p = nullptr;
        if (grow < M) {
            int r = rowidx ? rowidx[grow] : grow;
            p = A + (size_t)r * lda;
        }
        rowp[tid] = p;
    }
    __syncthreads();

    int am  = tid >> 3;     // 0..31, +32*i
    int ac2 = tid & 7;      // float2 column within k-tile
    int bkb = tid >> 6;     // 0..3, +4*i
    int bc  = tid & 63;

    int ty = tid >> 4, tx = tid & 15;
    float acc[8][4] = {};
    float2 areg[4];
    float  breg[4];

    int tiles = (kend - kbeg + 15) >> 4;

    // prologue: tile 0
    {
        int k0 = kbeg;
#pragma unroll
        for (int i = 0; i < 4; i++) {
            const float* p = rowp[am + 32 * i];
            int kc = k0 + ac2 * 2;
            areg[i] = (p != nullptr && kc < kend)
                    ? *reinterpret_cast<const float2*>(p + kc) : make_float2(0.f, 0.f);
        }
#pragma unroll
        for (int i = 0; i < 4; i++) {
            int kk = k0 + bkb + 4 * i, c = col0 + bc;
            breg[i] = (kk < kend && c < N) ? B[(size_t)kk * ldb + c] : 0.f;
        }
#pragma unroll
        for (int i = 0; i < 4; i++) {
            As[0][ac2 * 2][am + 32 * i]     = areg[i].x;
            As[0][ac2 * 2 + 1][am + 32 * i] = areg[i].y;
        }
#pragma unroll
        for (int i = 0; i < 4; i++) Bs[0][bkb + 4 * i][bc] = breg[i];
    }
    __syncthreads();

    for (int t = 0; t < tiles; t++) {
        int buf = t & 1;
        bool more = (t + 1 < tiles);
        if (more) {
            int k0 = kbeg + ((t + 1) << 4);
#pragma unroll
            for (int i = 0; i < 4; i++) {
                const float* p = rowp[am + 32 * i];
                int kc = k0 + ac2 * 2;
                areg[i] = (p != nullptr && kc < kend)
                        ? *reinterpret_cast<const float2*>(p + kc) : make_float2(0.f, 0.f);
            }
#pragma unroll
            for (int i = 0; i < 4; i++) {
                int kk = k0 + bkb + 4 * i, c = col0 + bc;
                breg[i] = (kk < kend && c < N) ? B[(size_t)kk * ldb + c] : 0.f;
            }
        }
#pragma unroll
        for (int kk = 0; kk < 16; kk++) {
            float4 a0v = *reinterpret_cast<const float4*>(&As[buf][kk][ty * 8]);
            float4 a1v = *reinterpret_cast<const float4*>(&As[buf][kk][ty * 8 + 4]);
            float4 bv  = *reinterpret_cast<const float4*>(&Bs[buf][kk][tx * 4]);
            float av[8] = {a0v.x, a0v.y, a0v.z, a0v.w, a1v.x, a1v.y, a1v.z, a1v.w};
            float bb[4] = {bv.x, bv.y, bv.z, bv.w};
#pragma unroll
            for (int i = 0; i < 8; i++)
#pragma unroll
                for (int j = 0; j < 4; j++)
                    acc[i][j] = fmaf(av[i], bb[j], acc[i][j]);
        }
        if (more) {
            int nb = 1 - buf;
#pragma unroll
            for (int i = 0; i < 4; i++) {
                As[nb][ac2 * 2][am + 32 * i]     = areg[i].x;
                As[nb][ac2 * 2 + 1][am + 32 * i] = areg[i].y;
            }
#pragma unroll
            for (int i = 0; i < 4; i++) Bs[nb][bkb + 4 * i][bc] = breg[i];
        }
        __syncthreads();
    }

    float* Cout = C + (size_t)blockIdx.z * (size_t)M * ldc;
    bool dorelu = (relu != 0) && (gridDim.z == 1);
#pragma unroll
    for (int i = 0; i < 8; i++) {
        int r = row0 + ty * 8 + i;
        if (r >= M) continue;
#pragma unroll
        for (int j = 0; j < 4; j++) {
            int c = col0 + tx * 4 + j;
            if (c < N) {
                float v = acc[i][j];
                if (dorelu) v = fmaxf(v, 0.f);
                Cout[(size_t)r * ldc + c] = v;
            }
        }
    }
}

// ---------------- split-K reduce: out[i] = (relu?)(sum_s part[s*MN + i]) ----------------
// Fixed ascending-s order: deterministic.
__global__ void reduce_kernel(const float* __restrict__ part, float* __restrict__ out,
                              int S, size_t MN, int relu) {
    size_t i4 = (size_t)blockIdx.x * blockDim.x + threadIdx.x;
    size_t n4 = MN >> 2;
    for (; i4 < n4; i4 += (size_t)gridDim.x * blockDim.x) {
        float4 s = reinterpret_cast<const float4*>(part)[i4];
        for (int z = 1; z < S; z++) {
            float4 v = reinterpret_cast<const float4*>(part + (size_t)z * MN)[i4];
            s.x += v.x; s.y += v.y; s.z += v.z; s.w += v.w;
        }
        if (relu) {
            s.x = fmaxf(s.x, 0.f); s.y = fmaxf(s.y, 0.f);
            s.z = fmaxf(s.z, 0.f); s.w = fmaxf(s.w, 0.f);
        }
        reinterpret_cast<float4*>(out)[i4] = s;
    }
    // scalar tail (MN may not be multiple of 4)
    size_t i = (n4 << 2) + (size_t)blockIdx.x * blockDim.x + threadIdx.x;
    if (i >= (n4 << 2) && i < MN) {
        float s = part[i];
        for (int z = 1; z < S; z++) s += part[(size_t)z * MN + i];
        if (relu) s = fmaxf(s, 0.f);
        out[i] = s;
    }
}

// ---------------- fused attention + gumbel-max sampling ----------------
// att math bitwise-identical to round-2 att_kernel; sampling identical to round-2
// sample_kernel (smem la values are the same floats).
__global__ __launch_bounds__(256, 3)
void attsample_kernel(const float* __restrict__ feature,
                      const int* __restrict__ edge,
                      const float* __restrict__ weight,
                      const int* __restrict__ nodes,
                      const float* __restrict__ u,
                      int n, int key_off,
                      int* __restrict__ frontier_next,
                      float* __restrict__ adj) {
    int b = blockIdx.x;
    __shared__ float2 us2[INPUT_DIM / 2];     // 301
    __shared__ float  la[SCOPE];
    __shared__ int    cols[KSAMP];
    int row = nodes[b];
    const float2* urow = reinterpret_cast<const float2*>(u + (size_t)b * INPUT_DIM);
    for (int i = threadIdx.x; i < INPUT_DIM / 2; i += blockDim.x) us2[i] = urow[i];
    __syncthreads();
    float a2 = d_a[2];
    int warp = threadIdx.x >> 5, lane = threadIdx.x & 31;
    const int* erow = edge + (size_t)row * SCOPE;
    const float* wrow = weight + (size_t)row * SCOPE;
    const bool has = lane < (INPUT_DIM / 2 - 288);   // lane < 13
#pragma unroll 1
    for (int i = 0; i < 16; i += 2) {
        int s0 = warp * 16 + i;
        int nb0 = erow[s0], nb1 = erow[s0 + 1];
        const float2* p0 = reinterpret_cast<const float2*>(feature + (size_t)nb0 * INPUT_DIM);
        const float2* p1 = reinterpret_cast<const float2*>(feature + (size_t)nb1 * INPUT_DIM);
        float2 v0[10], v1[10];
#pragma unroll
        for (int t = 0; t < 9; t++) {
            v0[t] = __ldg(p0 + lane + 32 * t);
            v1[t] = __ldg(p1 + lane + 32 * t);
        }
        if (has) {
            v0[9] = __ldg(p0 + lane + 288);
            v1[9] = __ldg(p1 + lane + 288);
        }
        float acc0 = 0.f, acc1 = 0.f;
#pragma unroll
        for (int t = 0; t < 9; t++) {
            float2 uv = us2[lane + 32 * t];
            acc0 = fmaf(uv.x, v0[t].x, acc0);
            acc0 = fmaf(uv.y, v0[t].y, acc0);
            acc1 = fmaf(uv.x, v1[t].x, acc1);
            acc1 = fmaf(uv.y, v1[t].y, acc1);
        }
        if (has) {
            float2 uv = us2[lane + 288];
            acc0 = fmaf(uv.x, v0[9].x, acc0);
            acc0 = fmaf(uv.y, v0[9].y, acc0);
            acc1 = fmaf(uv.x, v1[9].x, acc1);
            acc1 = fmaf(uv.y, v1[9].y, acc1);
        }
#pragma unroll
        for (int o = 16; o; o >>= 1) {
            acc0 += __shfl_down_sync(0xffffffffu, acc0, o);
            acc1 += __shfl_down_sync(0xffffffffu, acc1, o);
        }
        if (lane == 0) {
            la[s0]     = logf(fmaxf(acc0 + a2 * wrow[s0],     0.f) + 1e-9f);
            la[s0 + 1] = logf(fmaxf(acc1 + a2 * wrow[s0 + 1], 0.f) + 1e-9f);
        }
    }
    __syncthreads();

    unsigned k0 = d_keys[key_off], k1 = d_keys[key_off + 1];
    const float TINY = 1.1754943508222875e-38f;
    for (int k = warp; k < KSAMP; k += 8) {
        float best; int bidx;
#pragma unroll
        for (int t = 0; t < 4; t++) {
            int j = lane + 32 * t;
            // counter = linear index into gumbel tensor of shape (KSAMP, n, SCOPE)
            unsigned p = ((unsigned)(k * n + b)) * SCOPE + (unsigned)j;
            uint2 o = threefry(k0, k1, 0u, p);
            unsigned bits = o.x ^ o.y;
            float f = __uint_as_float((bits >> 9) | 0x3f800000u) - 1.0f;
            float uu = fmaxf(f + TINY, TINY);
            float g = -logf(-logf(uu));
            float v = la[j] + g;
            if (t == 0) { best = v; bidx = j; }
            else if (v > best) { best = v; bidx = j; }   // strict > keeps first max
        }
#pragma unroll
        for (int o2 = 16; o2; o2 >>= 1) {
            float v2 = __shfl_down_sync(0xffffffffu, best, o2);
            int   i2 = __shfl_down_sync(0xffffffffu, bidx, o2);
            if (v2 > best || (v2 == best && i2 < bidx)) { best = v2; bidx = i2; }
        }
        if (lane == 0) cols[k] = bidx;
    }
    __syncthreads();
    if (threadIdx.x == 0) {
        float ws[KSAMP]; float s = 0.f;
#pragma unroll
        for (int k = 0; k < KSAMP; k++) {
            int c = cols[k];
            float w = wrow[c];
            ws[k] = w; s += w;
            frontier_next[b * KSAMP + k] = erow[c];
        }
        float denom = s + 1e-9f;
#pragma unroll
        for (int k = 0; k < KSAMP; k++) adj[b * KSAMP + k] = ws[k] / denom;
    }
}

// ---------------- sparse aggregation: out[b,:] = sum_k adj[b,k] * X[row(b,k),:] --------
__global__ void aggregate_kernel(const float* __restrict__ X,
                                 const int* __restrict__ rowidx,
                                 const float* __restrict__ adj,
                                 float* __restrict__ out,
                                 int D, int ldx) {
    int b = blockIdx.x;
    __shared__ const float* rows[KSAMP];
    __shared__ float w[KSAMP];
    if (threadIdx.x < KSAMP) {
        int e = b * KSAMP + threadIdx.x;
        int r = rowidx ? rowidx[e] : e;
        rows[threadIdx.x] = X + (size_t)r * ldx;
        w[threadIdx.x] = adj[e];
    }
    __syncthreads();
    float2* orow = reinterpret_cast<float2*>(out + (size_t)b * D);
    int D2 = D >> 1;
    for (int d = threadIdx.x; d < D2; d += blockDim.x) {
        float2 s = make_float2(0.f, 0.f);
#pragma unroll
        for (int k = 0; k < KSAMP; k++) {
            float2 v = reinterpret_cast<const float2*>(rows[k])[d];
            s.x = fmaf(w[k], v.x, s.x);
            s.y = fmaf(w[k], v.y, s.y);
        }
        orow[d] = s;
    }
}

// ---------------- launch ----------------
static inline dim3 gemm_grid(int M, int N, int S) {
    return dim3((N + 63) / 64, (M + 127) / 128, S);
}
static inline int red_grid(size_t MN) {
    size_t b = ((MN >> 2) + 255) / 256;
    return (int)(b < 1 ? 1 : (b > 2048 ? 2048 : b));
}

extern "C" void kernel_launch(void* const* d_in, const int* in_sizes, int n_in,
                              void* d_out, int out_size) {
    const int*   ids     = (const int*)d_in[0];
    const float* feature = (const float*)d_in[1];
    const int*   edge    = (const int*)d_in[2];
    const float* weight  = (const float*)d_in[3];
    const float* sW      = (const float*)d_in[4];
    const float* sW2     = (const float*)d_in[5];
    const float* sa      = (const float*)d_in[6];
    const float* W1      = (const float*)d_in[7];
    const float* W2      = (const float*)d_in[8];
    float* out = (float*)d_out;

    float *pM, *pWcat, *pWt, *pu, *pPart, *pXa, *pX1, *pXb, *pA0, *pA1;
    int *pf1, *pf2;
    cudaGetSymbolAddress((void**)&pM,    d_M);
    cudaGetSymbolAddress((void**)&pWcat, d_Wcat);
    cudaGetSymbolAddress((void**)&pWt,   d_Wt);
    cudaGetSymbolAddress((void**)&pu,    d_u);
    cudaGetSymbolAddress((void**)&pPart, d_part);
    cudaGetSymbolAddress((void**)&pXa,   d_Xa);
    cudaGetSymbolAddress((void**)&pX1,   d_X1);
    cudaGetSymbolAddress((void**)&pXb,   d_Xb);
    cudaGetSymbolAddress((void**)&pA0,   d_adjL0);
    cudaGetSymbolAddress((void**)&pA1,   d_adjL1);
    cudaGetSymbolAddress((void**)&pf1,   d_front1);
    cudaGetSymbolAddress((void**)&pf2,   d_front2);

    setup_kernel<<<1, 1>>>(sa);
    prep_kernel<<<INPUT_DIM, 256>>>(sW, sW2);

    // M = Wcat @ Wt   (602 x 602, K=512), split-K S=4 (chunk 128) -> 200 CTAs
    {
        size_t MN = (size_t)INPUT_DIM * INPUT_DIM;
        sgemm_kernel<<<gemm_grid(INPUT_DIM, INPUT_DIM, 4), 256>>>(
            pWcat, nullptr, pWt, pPart,
            INPUT_DIM, INPUT_DIM, KCAT, KCAT, INPUT_DIM, INPUT_DIM, 0, 128);
        reduce_kernel<<<red_grid(MN), 256>>>(pPart, pM, 4, MN, 0);
    }

    // ---- step i=0 (layer 1), n = 256, frontier = ids ----
    // u0 = F[ids] @ M  (256 x 602, K=602), split-K S=8 (chunk 80) -> 160 CTAs
    {
        size_t MN = (size_t)BATCH * INPUT_DIM;
        sgemm_kernel<<<gemm_grid(BATCH, INPUT_DIM, 8), 256>>>(
            feature, ids, pM, pPart,
            BATCH, INPUT_DIM, INPUT_DIM, INPUT_DIM, INPUT_DIM, INPUT_DIM, 0, 80);
        reduce_kernel<<<red_grid(MN), 256>>>(pPart, pu, 8, MN, 0);
    }
    attsample_kernel<<<BATCH, 256>>>(feature, edge, weight, ids, pu,
                                     BATCH, 0, pf1, pA1);

    // ---- step i=1 (layer 0), n = 2560 -> 200 CTAs, single wave, direct ----
    sgemm_kernel<<<gemm_grid(N1, INPUT_DIM, 1), 256>>>(
        feature, pf1, pM, pu,
        N1, INPUT_DIM, INPUT_DIM, INPUT_DIM, INPUT_DIM, INPUT_DIM, 0, INPUT_DIM);
    attsample_kernel<<<N1, 256>>>(feature, edge, weight, pf1, pu,
                                  N1, 2, pf2, pA0);

    // ---- aggregation: layer 0 ----
    aggregate_kernel<<<N1, 256>>>(feature, pf2, pA0, pXa, INPUT_DIM, INPUT_DIM);
    // X1 = relu(Xa @ W1)  (2560 x 256, K=602), split-K S=2 (chunk 304) -> 160 CTAs
    {
        size_t MN = (size_t)N1 * HIDDEN_DIM;
        sgemm_kernel<<<gemm_grid(N1, HIDDEN_DIM, 2), 256>>>(
            pXa, nullptr, W1, pPart,
            N1, HIDDEN_DIM, INPUT_DIM, INPUT_DIM, HIDDEN_DIM, HIDDEN_DIM, 1, 304);
        reduce_kernel<<<red_grid(MN), 256>>>(pPart, pX1, 2, MN, 1);
    }

    // ---- aggregation: layer 1 ----
    aggregate_kernel<<<BATCH, 256>>>(pX1, nullptr, pA1, pXb, HIDDEN_DIM, HIDDEN_DIM);
    // out = Xb @ W2  (256 x 41, K=256), split-K S=8 (chunk 32) -> 16 CTAs
    {
        size_t MN = (size_t)BATCH * OUTPUT_DIM;
        sgemm_kernel<<<gemm_grid(BATCH, OUTPUT_DIM, 8), 256>>>(
            pXb, nullptr, W2, pPart,
            BATCH, OUTPUT_DIM, HIDDEN_DIM, HIDDEN_DIM, OUTPUT_DIM, OUTPUT_DIM, 0, 32);
        reduce_kernel<<<red_grid(MN), 256>>>(pPart, out, 8, MN, 0);
    }
}

// round 8
// speedup vs baseline: 1.4109x; 1.0305x over previous
#include <cuda_runtime.h>
#include <cstdint>
#include <cstddef>

// ---------------- problem constants ----------------
#define NODE_NUM 232965
#define INPUT_DIM 602
#define HIDDEN_DIM 256
#define OUTPUT_DIM 41
#define BATCH 256
#define SCOPE 128
#define KSAMP 10
#define N1 2560      /* BATCH*KSAMP */
#define N2 25600     /* N1*KSAMP */
#define KCAT 512     /* 2*HIDDEN_DIM */

// ---------------- device scratch (static; no allocations) ----------------
__device__ float    d_M[INPUT_DIM * INPUT_DIM];       // a0*W W^T + a1*W2 W2^T
__device__ float    d_Wcat[INPUT_DIM * KCAT];         // [a0*W | a1*W2]
__device__ float    d_Wt[KCAT * INPUT_DIM];           // [W ; W2]^T (unscaled)
__device__ float    d_u[N1 * INPUT_DIM];              // projected src features
__device__ float    d_part[3100000];                  // split-K partials
__device__ int      d_front1[N1];
__device__ float    d_adjL1[BATCH * KSAMP];           // adj_list[1]
__device__ float    d_adjL0[N1 * KSAMP];              // adj_list[0]
__device__ float    d_Xa[N1 * INPUT_DIM];
__device__ float    d_X1[N1 * HIDDEN_DIM];
__device__ float    d_Xb[BATCH * HIDDEN_DIM];
__device__ float    d_a[3];
__device__ unsigned d_keys[4];                        // sk1.{hi,lo}, sk2.{hi,lo}

// ---------------- threefry2x32 (JAX-exact) ----------------
__device__ __forceinline__ uint2 threefry(unsigned k0, unsigned k1,
                                          unsigned c0, unsigned c1) {
    unsigned ks2 = k0 ^ k1 ^ 0x1BD11BDAu;
    unsigned x0 = c0 + k0, x1 = c1 + k1;
#define TF_R(r) { x0 += x1; x1 = (x1 << (r)) | (x1 >> (32 - (r))); x1 ^= x0; }
    TF_R(13) TF_R(15) TF_R(26) TF_R(6)
    x0 += k1;  x1 += ks2 + 1u;
    TF_R(17) TF_R(29) TF_R(16) TF_R(24)
    x0 += ks2; x1 += k0 + 2u;
    TF_R(13) TF_R(15) TF_R(26) TF_R(6)
    x0 += k0;  x1 += k1 + 3u;
    TF_R(17) TF_R(29) TF_R(16) TF_R(24)
    x0 += k1;  x1 += ks2 + 4u;
    TF_R(13) TF_R(15) TF_R(26) TF_R(6)
    x0 += ks2; x1 += k0 + 5u;
#undef TF_R
    return make_uint2(x0, x1);
}

// ---------------- setup: softmax(a), key chain ----------------
__global__ void setup_kernel(const float* __restrict__ sa) {
    float v0 = sa[0], v1 = sa[1], v2 = sa[2];
    float m = fmaxf(v0, fmaxf(v1, v2));
    float e0 = expf(v0 - m), e1 = expf(v1 - m), e2 = expf(v2 - m);
    float s = e0 + e1 + e2;
    d_a[0] = e0 / s; d_a[1] = e1 / s; d_a[2] = e2 / s;
    // key(42) -> (0,42). partitionable split: child i = TF(key, 0, i)
    uint2 key1 = threefry(0u, 42u, 0u, 0u);
    uint2 sk1  = threefry(0u, 42u, 0u, 1u);
    uint2 sk2  = threefry(key1.x, key1.y, 0u, 1u);
    d_keys[0] = sk1.x; d_keys[1] = sk1.y;
    d_keys[2] = sk2.x; d_keys[3] = sk2.y;
}

// ---------------- prep: Wcat[f][k] = a{0,1}*W{1,2}[f][k'], Wt[k][f] = W{1,2}[f][k'] ----
__global__ void prep_kernel(const float* __restrict__ W, const float* __restrict__ W2) {
    int f = blockIdx.x;
    float a0 = d_a[0], a1 = d_a[1];
    for (int k = threadIdx.x; k < KCAT; k += blockDim.x) {
        float v  = (k < HIDDEN_DIM) ? W[(size_t)f * HIDDEN_DIM + k]
                                    : W2[(size_t)f * HIDDEN_DIM + (k - HIDDEN_DIM)];
        float sc = (k < HIDDEN_DIM) ? a0 : a1;
        d_Wcat[(size_t)f * KCAT + k] = v * sc;
        d_Wt[(size_t)k * INPUT_DIM + f] = v;
    }
}

// ---------------- fast SGEMM with split-K: C = gatherA(A)[M,K] @ B[K,N] ----------------
// BM=128, BN=64, BK=16, 256 threads, 8x4 per thread, double-buffered.
// gridDim.z = S splits; split z covers K range [z*chunk, min(K,(z+1)*chunk)).
// S>1: writes partials (no relu) to C + z*M*ldc; S==1: writes final with relu.
__global__ __launch_bounds__(256, 2)
void sgemm_kernel(const float* __restrict__ A, const int* __restrict__ rowidx,
                  const float* __restrict__ B, float* __restrict__ C,
                  int M, int N, int K, int lda, int ldb, int ldc,
                  int relu, int chunk) {
    __shared__ float As[2][16][132];
    __shared__ float Bs[2][16][64];
    __shared__ const float* rowp[128];
    int tid = threadIdx.x;
    int row0 = blockIdx.y * 128, col0 = blockIdx.x * 64;
    int kbeg = blockIdx.z * chunk;
    int kend = min(K, kbeg + chunk);

    if (tid < 128) {
        int grow = row0 + tid;
        const float* p = nullptr;
        if (grow < M) {
            int r = rowidx ? rowidx[grow] : grow;
            p = A + (size_t)r * lda;
        }
        rowp[tid] = p;
    }
    __syncthreads();

    int am  = tid >> 3;     // 0..31, +32*i
    int ac2 = tid & 7;      // float2 column within k-tile
    int bkb = tid >> 6;     // 0..3, +4*i
    int bc  = tid & 63;

    int ty = tid >> 4, tx = tid & 15;
    float acc[8][4] = {};
    float2 areg[4];
    float  breg[4];

    int tiles = (kend - kbeg + 15) >> 4;

    // prologue: tile 0
    {
        int k0 = kbeg;
#pragma unroll
        for (int i = 0; i < 4; i++) {
            const float* p = rowp[am + 32 * i];
            int kc = k0 + ac2 * 2;
            areg[i] = (p != nullptr && kc < kend)
                    ? *reinterpret_cast<const float2*>(p + kc) : make_float2(0.f, 0.f);
        }
#pragma unroll
        for (int i = 0; i < 4; i++) {
            int kk = k0 + bkb + 4 * i, c = col0 + bc;
            breg[i] = (kk < kend && c < N) ? B[(size_t)kk * ldb + c] : 0.f;
        }
#pragma unroll
        for (int i = 0; i < 4; i++) {
            As[0][ac2 * 2][am + 32 * i]     = areg[i].x;
            As[0][ac2 * 2 + 1][am + 32 * i] = areg[i].y;
        }
#pragma unroll
        for (int i = 0; i < 4; i++) Bs[0][bkb + 4 * i][bc] = breg[i];
    }
    __syncthreads();

    for (int t = 0; t < tiles; t++) {
        int buf = t & 1;
        bool more = (t + 1 < tiles);
        if (more) {
            int k0 = kbeg + ((t + 1) << 4);
#pragma unroll
            for (int i = 0; i < 4; i++) {
                const float* p = rowp[am + 32 * i];
                int kc = k0 + ac2 * 2;
                areg[i] = (p != nullptr && kc < kend)
                        ? *reinterpret_cast<const float2*>(p + kc) : make_float2(0.f, 0.f);
            }
#pragma unroll
            for (int i = 0; i < 4; i++) {
                int kk = k0 + bkb + 4 * i, c = col0 + bc;
                breg[i] = (kk < kend && c < N) ? B[(size_t)kk * ldb + c] : 0.f;
            }
        }
#pragma unroll
        for (int kk = 0; kk < 16; kk++) {
            float4 a0v = *reinterpret_cast<const float4*>(&As[buf][kk][ty * 8]);
            float4 a1v = *reinterpret_cast<const float4*>(&As[buf][kk][ty * 8 + 4]);
            float4 bv  = *reinterpret_cast<const float4*>(&Bs[buf][kk][tx * 4]);
            float av[8] = {a0v.x, a0v.y, a0v.z, a0v.w, a1v.x, a1v.y, a1v.z, a1v.w};
            float bb[4] = {bv.x, bv.y, bv.z, bv.w};
#pragma unroll
            for (int i = 0; i < 8; i++)
#pragma unroll
                for (int j = 0; j < 4; j++)
                    acc[i][j] = fmaf(av[i], bb[j], acc[i][j]);
        }
        if (more) {
            int nb = 1 - buf;
#pragma unroll
            for (int i = 0; i < 4; i++) {
                As[nb][ac2 * 2][am + 32 * i]     = areg[i].x;
                As[nb][ac2 * 2 + 1][am + 32 * i] = areg[i].y;
            }
#pragma unroll
            for (int i = 0; i < 4; i++) Bs[nb][bkb + 4 * i][bc] = breg[i];
        }
        __syncthreads();
    }

    float* Cout = C + (size_t)blockIdx.z * (size_t)M * ldc;
    bool dorelu = (relu != 0) && (gridDim.z == 1);
#pragma unroll
    for (int i = 0; i < 8; i++) {
        int r = row0 + ty * 8 + i;
        if (r >= M) continue;
#pragma unroll
        for (int j = 0; j < 4; j++) {
            int c = col0 + tx * 4 + j;
            if (c < N) {
                float v = acc[i][j];
                if (dorelu) v = fmaxf(v, 0.f);
                Cout[(size_t)r * ldc + c] = v;
            }
        }
    }
}

// ---------------- split-K reduce: out[i] = (relu?)(sum_s part[s*MN + i]) ----------------
// Fixed ascending-s order: deterministic.
__global__ void reduce_kernel(const float* __restrict__ part, float* __restrict__ out,
                              int S, size_t MN, int relu) {
    size_t i4 = (size_t)blockIdx.x * blockDim.x + threadIdx.x;
    size_t n4 = MN >> 2;
    for (; i4 < n4; i4 += (size_t)gridDim.x * blockDim.x) {
        float4 s = reinterpret_cast<const float4*>(part)[i4];
        for (int z = 1; z < S; z++) {
            float4 v = reinterpret_cast<const float4*>(part + (size_t)z * MN)[i4];
            s.x += v.x; s.y += v.y; s.z += v.z; s.w += v.w;
        }
        if (relu) {
            s.x = fmaxf(s.x, 0.f); s.y = fmaxf(s.y, 0.f);
            s.z = fmaxf(s.z, 0.f); s.w = fmaxf(s.w, 0.f);
        }
        reinterpret_cast<float4*>(out)[i4] = s;
    }
    // scalar tail (MN may not be multiple of 4)
    size_t i = (n4 << 2) + (size_t)blockIdx.x * blockDim.x + threadIdx.x;
    if (i >= (n4 << 2) && i < MN) {
        float s = part[i];
        for (int z = 1; z < S; z++) s += part[(size_t)z * MN + i];
        if (relu) s = fmaxf(s, 0.f);
        out[i] = s;
    }
}

// ---------------- fused attention + gumbel-max sampling (+ optional aggregation) -------
// att math bitwise-identical to round-2 att_kernel; sampling identical.
// If outX != nullptr: also computes outX[b,:] = sum_k adj[b,k]*feature[sel_k,:]
// (same ascending-k fmaf order as aggregate_kernel), and skips frontier writes.
__global__ __launch_bounds__(256, 3)
void attsample_kernel(const float* __restrict__ feature,
                      const int* __restrict__ edge,
                      const float* __restrict__ weight,
                      const int* __restrict__ nodes,
                      const float* __restrict__ u,
                      int n, int key_off,
                      int* __restrict__ frontier_next,
                      float* __restrict__ adj,
                      float* __restrict__ outX) {
    int b = blockIdx.x;
    __shared__ float2 us2[INPUT_DIM / 2];     // 301
    __shared__ float  la[SCOPE];
    __shared__ int    cols[KSAMP];
    __shared__ int    selid[KSAMP];
    __shared__ float  adjw[KSAMP];
    int row = nodes[b];
    const float2* urow = reinterpret_cast<const float2*>(u + (size_t)b * INPUT_DIM);
    for (int i = threadIdx.x; i < INPUT_DIM / 2; i += blockDim.x) us2[i] = urow[i];
    __syncthreads();
    float a2 = d_a[2];
    int warp = threadIdx.x >> 5, lane = threadIdx.x & 31;
    const int* erow = edge + (size_t)row * SCOPE;
    const float* wrow = weight + (size_t)row * SCOPE;
    const bool has = lane < (INPUT_DIM / 2 - 288);   // lane < 13
#pragma unroll 1
    for (int i = 0; i < 16; i += 2) {
        int s0 = warp * 16 + i;
        int nb0 = erow[s0], nb1 = erow[s0 + 1];
        const float2* p0 = reinterpret_cast<const float2*>(feature + (size_t)nb0 * INPUT_DIM);
        const float2* p1 = reinterpret_cast<const float2*>(feature + (size_t)nb1 * INPUT_DIM);
        float2 v0[10], v1[10];
#pragma unroll
        for (int t = 0; t < 9; t++) {
            v0[t] = __ldg(p0 + lane + 32 * t);
            v1[t] = __ldg(p1 + lane + 32 * t);
        }
        if (has) {
            v0[9] = __ldg(p0 + lane + 288);
            v1[9] = __ldg(p1 + lane + 288);
        }
        float acc0 = 0.f, acc1 = 0.f;
#pragma unroll
        for (int t = 0; t < 9; t++) {
            float2 uv = us2[lane + 32 * t];
            acc0 = fmaf(uv.x, v0[t].x, acc0);
            acc0 = fmaf(uv.y, v0[t].y, acc0);
            acc1 = fmaf(uv.x, v1[t].x, acc1);
            acc1 = fmaf(uv.y, v1[t].y, acc1);
        }
        if (has) {
            float2 uv = us2[lane + 288];
            acc0 = fmaf(uv.x, v0[9].x, acc0);
            acc0 = fmaf(uv.y, v0[9].y, acc0);
            acc1 = fmaf(uv.x, v1[9].x, acc1);
            acc1 = fmaf(uv.y, v1[9].y, acc1);
        }
#pragma unroll
        for (int o = 16; o; o >>= 1) {
            acc0 += __shfl_down_sync(0xffffffffu, acc0, o);
            acc1 += __shfl_down_sync(0xffffffffu, acc1, o);
        }
        if (lane == 0) {
            la[s0]     = logf(fmaxf(acc0 + a2 * wrow[s0],     0.f) + 1e-9f);
            la[s0 + 1] = logf(fmaxf(acc1 + a2 * wrow[s0 + 1], 0.f) + 1e-9f);
        }
    }
    __syncthreads();

    unsigned k0 = d_keys[key_off], k1 = d_keys[key_off + 1];
    const float TINY = 1.1754943508222875e-38f;
    for (int k = warp; k < KSAMP; k += 8) {
        float best; int bidx;
#pragma unroll
        for (int t = 0; t < 4; t++) {
            int j = lane + 32 * t;
            // counter = linear index into gumbel tensor of shape (KSAMP, n, SCOPE)
            unsigned p = ((unsigned)(k * n + b)) * SCOPE + (unsigned)j;
            uint2 o = threefry(k0, k1, 0u, p);
            unsigned bits = o.x ^ o.y;
            float f = __uint_as_float((bits >> 9) | 0x3f800000u) - 1.0f;
            float uu = fmaxf(f + TINY, TINY);
            float g = -logf(-logf(uu));
            float v = la[j] + g;
            if (t == 0) { best = v; bidx = j; }
            else if (v > best) { best = v; bidx = j; }   // strict > keeps first max
        }
#pragma unroll
        for (int o2 = 16; o2; o2 >>= 1) {
            float v2 = __shfl_down_sync(0xffffffffu, best, o2);
            int   i2 = __shfl_down_sync(0xffffffffu, bidx, o2);
            if (v2 > best || (v2 == best && i2 < bidx)) { best = v2; bidx = i2; }
        }
        if (lane == 0) cols[k] = bidx;
    }
    __syncthreads();
    if (threadIdx.x == 0) {
        float ws[KSAMP]; float s = 0.f;
#pragma unroll
        for (int k = 0; k < KSAMP; k++) {
            int c = cols[k];
            float w = wrow[c];
            ws[k] = w; s += w;
            int nid = erow[c];
            selid[k] = nid;
            if (frontier_next) frontier_next[b * KSAMP + k] = nid;
        }
        float denom = s + 1e-9f;
#pragma unroll
        for (int k = 0; k < KSAMP; k++) {
            float aw = ws[k] / denom;
            adjw[k] = aw;
            adj[b * KSAMP + k] = aw;
        }
    }
    if (outX) {
        __syncthreads();
        const float2* rows[KSAMP];
        float w[KSAMP];
#pragma unroll
        for (int k = 0; k < KSAMP; k++) {
            rows[k] = reinterpret_cast<const float2*>(feature + (size_t)selid[k] * INPUT_DIM);
            w[k] = adjw[k];
        }
        float2* orow = reinterpret_cast<float2*>(outX + (size_t)b * INPUT_DIM);
        for (int d = threadIdx.x; d < INPUT_DIM / 2; d += blockDim.x) {
            float2 s2 = make_float2(0.f, 0.f);
#pragma unroll
            for (int k = 0; k < KSAMP; k++) {
                float2 v = rows[k][d];
                s2.x = fmaf(w[k], v.x, s2.x);
                s2.y = fmaf(w[k], v.y, s2.y);
            }
            orow[d] = s2;
        }
    }
}

// ---------------- sparse aggregation: out[b,:] = sum_k adj[b,k] * X[row(b,k),:] --------
__global__ void aggregate_kernel(const float* __restrict__ X,
                                 const int* __restrict__ rowidx,
                                 const float* __restrict__ adj,
                                 float* __restrict__ out,
                                 int D, int ldx) {
    int b = blockIdx.x;
    __shared__ const float* rows[KSAMP];
    __shared__ float w[KSAMP];
    if (threadIdx.x < KSAMP) {
        int e = b * KSAMP + threadIdx.x;
        int r = rowidx ? rowidx[e] : e;
        rows[threadIdx.x] = X + (size_t)r * ldx;
        w[threadIdx.x] = adj[e];
    }
    __syncthreads();
    float2* orow = reinterpret_cast<float2*>(out + (size_t)b * D);
    int D2 = D >> 1;
    for (int d = threadIdx.x; d < D2; d += blockDim.x) {
        float2 s = make_float2(0.f, 0.f);
#pragma unroll
        for (int k = 0; k < KSAMP; k++) {
            float2 v = reinterpret_cast<const float2*>(rows[k])[d];
            s.x = fmaf(w[k], v.x, s.x);
            s.y = fmaf(w[k], v.y, s.y);
        }
        orow[d] = s;
    }
}

// ---------------- launch ----------------
static inline dim3 gemm_grid(int M, int N, int S) {
    return dim3((N + 63) / 64, (M + 127) / 128, S);
}
static inline int red_grid(size_t MN) {
    size_t b = ((MN >> 2) + 255) / 256;
    return (int)(b < 1 ? 1 : (b > 2048 ? 2048 : b));
}

extern "C" void kernel_launch(void* const* d_in, const int* in_sizes, int n_in,
                              void* d_out, int out_size) {
    const int*   ids     = (const int*)d_in[0];
    const float* feature = (const float*)d_in[1];
    const int*   edge    = (const int*)d_in[2];
    const float* weight  = (const float*)d_in[3];
    const float* sW      = (const float*)d_in[4];
    const float* sW2     = (const float*)d_in[5];
    const float* sa      = (const float*)d_in[6];
    const float* W1      = (const float*)d_in[7];
    const float* W2      = (const float*)d_in[8];
    float* out = (float*)d_out;

    float *pM, *pWcat, *pWt, *pu, *pPart, *pXa, *pX1, *pXb, *pA0, *pA1;
    int *pf1;
    cudaGetSymbolAddress((void**)&pM,    d_M);
    cudaGetSymbolAddress((void**)&pWcat, d_Wcat);
    cudaGetSymbolAddress((void**)&pWt,   d_Wt);
    cudaGetSymbolAddress((void**)&pu,    d_u);
    cudaGetSymbolAddress((void**)&pPart, d_part);
    cudaGetSymbolAddress((void**)&pXa,   d_Xa);
    cudaGetSymbolAddress((void**)&pX1,   d_X1);
    cudaGetSymbolAddress((void**)&pXb,   d_Xb);
    cudaGetSymbolAddress((void**)&pA0,   d_adjL0);
    cudaGetSymbolAddress((void**)&pA1,   d_adjL1);
    cudaGetSymbolAddress((void**)&pf1,   d_front1);

    setup_kernel<<<1, 1>>>(sa);
    prep_kernel<<<INPUT_DIM, 256>>>(sW, sW2);

    // M = Wcat @ Wt   (602 x 602, K=512), split-K S=4 (chunk 128) -> 200 CTAs
    {
        size_t MN = (size_t)INPUT_DIM * INPUT_DIM;
        sgemm_kernel<<<gemm_grid(INPUT_DIM, INPUT_DIM, 4), 256>>>(
            pWcat, nullptr, pWt, pPart,
            INPUT_DIM, INPUT_DIM, KCAT, KCAT, INPUT_DIM, INPUT_DIM, 0, 128);
        reduce_kernel<<<red_grid(MN), 256>>>(pPart, pM, 4, MN, 0);
    }

    // ---- step i=0 (layer 1), n = 256, frontier = ids ----
    // u0 = F[ids] @ M  (256 x 602, K=602), split-K S=8 (chunk 80) -> 160 CTAs
    {
        size_t MN = (size_t)BATCH * INPUT_DIM;
        sgemm_kernel<<<gemm_grid(BATCH, INPUT_DIM, 8), 256>>>(
            feature, ids, pM, pPart,
            BATCH, INPUT_DIM, INPUT_DIM, INPUT_DIM, INPUT_DIM, INPUT_DIM, 0, 80);
        reduce_kernel<<<red_grid(MN), 256>>>(pPart, pu, 8, MN, 0);
    }
    attsample_kernel<<<BATCH, 256>>>(feature, edge, weight, ids, pu,
                                     BATCH, 0, pf1, pA1, nullptr);

    // ---- step i=1 (layer 0), n = 2560 ----
    // u1 = F[front1] @ M  (2560 x 602, K=602), split-K S=2 (chunk 304) -> 400 CTAs
    {
        size_t MN = (size_t)N1 * INPUT_DIM;
        sgemm_kernel<<<gemm_grid(N1, INPUT_DIM, 2), 256>>>(
            feature, pf1, pM, pPart,
            N1, INPUT_DIM, INPUT_DIM, INPUT_DIM, INPUT_DIM, INPUT_DIM, 0, 304);
        reduce_kernel<<<red_grid(MN), 256>>>(pPart, pu, 2, MN, 0);
    }
    // fused att + sample + layer-0 aggregation (Xa) — frontier not materialized
    attsample_kernel<<<N1, 256>>>(feature, edge, weight, pf1, pu,
                                  N1, 2, nullptr, pA0, pXa);

    // X1 = relu(Xa @ W1)  (2560 x 256, K=602), split-K S=2 (chunk 304) -> 160 CTAs
    {
        size_t MN = (size_t)N1 * HIDDEN_DIM;
        sgemm_kernel<<<gemm_grid(N1, HIDDEN_DIM, 2), 256>>>(
            pXa, nullptr, W1, pPart,
            N1, HIDDEN_DIM, INPUT_DIM, INPUT_DIM, HIDDEN_DIM, HIDDEN_DIM, 1, 304);
        reduce_kernel<<<red_grid(MN), 256>>>(pPart, pX1, 2, MN, 1);
    }

    // ---- aggregation: layer 1 ----
    aggregate_kernel<<<BATCH, 256>>>(pX1, nullptr, pA1, pXb, HIDDEN_DIM, HIDDEN_DIM);
    // out = Xb @ W2  (256 x 41, K=256), split-K S=8 (chunk 32) -> 16 CTAs
    {
        size_t MN = (size_t)BATCH * OUTPUT_DIM;
        sgemm_kernel<<<gemm_grid(BATCH, OUTPUT_DIM, 8), 256>>>(
            pXb, nullptr, W2, pPart,
            BATCH, OUTPUT_DIM, HIDDEN_DIM, HIDDEN_DIM, OUTPUT_DIM, OUTPUT_DIM, 0, 32);
        reduce_kernel<<<red_grid(MN), 256>>>(pPart, out, 8, MN, 0);
    }
}